// round 13
// baseline (speedup 1.0000x reference)
#include <cuda_runtime.h>
#include <cuda_fp16.h>
#include <cstdint>
#include <math.h>

// Problem constants (fixed for this dataset)
#define MAXN 50000
#define MAXE 800000
#define MAXG 512
#define HID  256
#define CHUNK_ROWS 12544          // 98 tiles of 128; 4 chunks cover >= N

// ---------------------------------------------------------------------------
// Streams/events for cross-stream overlap. Created at static-init (host-side
// objects; no device allocation inside kernel_launch -> mem deltas stay 0).
struct StreamPack {
    cudaStream_t s2;
    cudaEvent_t evA[12];   // per layer (3) per chunk (4)
    cudaEvent_t evJ[3];    // per-layer join
    StreamPack() {
        cudaStreamCreateWithFlags(&s2, cudaStreamNonBlocking);
        for (int i = 0; i < 12; i++) cudaEventCreateWithFlags(&evA[i], cudaEventDisableTiming);
        for (int i = 0; i < 3;  i++) cudaEventCreateWithFlags(&evJ[i], cudaEventDisableTiming);
    }
};
static StreamPack g_sp;

// ---------------------------------------------------------------------------
// Scratch (__device__ globals: allocation-free per harness rules)
__device__ __half g_A[(size_t)MAXN * HID];            // agg output, fp16
__device__ __half g_H[(size_t)MAXN * HID];            // hidden state (layers 1,3 input)
__device__ __half g_H2[(size_t)MAXN * HID];           // layer-2 output (avoids in-place RAW)
__device__ __half g_x16[(size_t)MAXN * 128];          // fp16 copy of input x
__device__ float g_dis[MAXN];
__device__ int   g_counts[MAXN];
__device__ int   g_offs[MAXN + 1];
__device__ int   g_wptr[MAXN];
__device__ int   g_csr[MAXE];
__device__ float g_sums[MAXG * HID];
__device__ int   g_gcnt[MAXG];
__device__ int   g_bsum[64];
// transposed weights: [N=256 rows][K cols], K-major fp16
__device__ __half g_W1t[256 * 128];
__device__ __half g_W2t[256 * 256];
__device__ __half g_W3t[256 * 256];

// ---------------------------------------------------------------------------
// base-ISA tensor helpers (mma.sync / ldmatrix / cp.async)
__device__ __forceinline__ void ldsm_x4(uint32_t& r0, uint32_t& r1, uint32_t& r2, uint32_t& r3,
                                        uint32_t addr) {
    asm volatile("ldmatrix.sync.aligned.m8n8.x4.shared.b16 {%0,%1,%2,%3}, [%4];"
                 : "=r"(r0), "=r"(r1), "=r"(r2), "=r"(r3) : "r"(addr));
}
__device__ __forceinline__ void mma_fp16(float* c, const uint32_t* a, uint32_t b0, uint32_t b1) {
    asm volatile("mma.sync.aligned.m16n8k16.row.col.f32.f16.f16.f32 "
                 "{%0,%1,%2,%3}, {%4,%5,%6,%7}, {%8,%9}, {%0,%1,%2,%3};"
                 : "+f"(c[0]), "+f"(c[1]), "+f"(c[2]), "+f"(c[3])
                 : "r"(a[0]), "r"(a[1]), "r"(a[2]), "r"(a[3]), "r"(b0), "r"(b1));
}
__device__ __forceinline__ void cp_async16(uint32_t smem_addr, const void* gptr, uint32_t src_sz) {
    asm volatile("cp.async.cg.shared.global [%0], [%1], 16, %2;"
                 :: "r"(smem_addr), "l"(gptr), "r"(src_sz) : "memory");
}
#define CP_COMMIT() asm volatile("cp.async.commit_group;" ::: "memory")
#define CP_WAIT(n)  asm volatile("cp.async.wait_group %0;" :: "n"(n) : "memory")
__device__ __forceinline__ uint32_t smem_u32(const void* p) {
    uint32_t a;
    asm("{ .reg .u64 t; cvta.to.shared.u64 t, %1; cvt.u32.u64 %0, t; }" : "=r"(a) : "l"(p));
    return a;
}

// ---------------------------------------------------------------------------
// 0. zero-init
__global__ void init_kernel(int n_nodes, int n_graphs) {
    int i = blockIdx.x * blockDim.x + threadIdx.x;
    int total = n_nodes + n_graphs + n_graphs * HID;
    for (; i < total; i += gridDim.x * blockDim.x) {
        if (i < n_nodes) g_counts[i] = 0;
        else if (i < n_nodes + n_graphs) g_gcnt[i - n_nodes] = 0;
        else g_sums[i - n_nodes - n_graphs] = 0.0f;
    }
}
// 1. in-degree counts + per-graph node counts (merged)
__global__ void count_gcnt(const int* __restrict__ ei, const int* __restrict__ batch,
                           int E, int N) {
    int i = blockIdx.x * blockDim.x + threadIdx.x;
    if (i < E) atomicAdd(&g_counts[ei[E + i]], 1);
    else if (i < E + N) atomicAdd(&g_gcnt[batch[i - E]], 1);
}
// 1b. convert input x to fp16
__global__ void xhalf_kernel(const float* __restrict__ x, __half* __restrict__ o, int total4) {
    int i = blockIdx.x * blockDim.x + threadIdx.x;
    if (i < total4) {
        float4 f = ((const float4*)x)[i];
        __half2 a = __floats2half2_rn(f.x, f.y);
        __half2 b = __floats2half2_rn(f.z, f.w);
        uint2 u; u.x = *(uint32_t*)&a; u.y = *(uint32_t*)&b;
        ((uint2*)o)[i] = u;
    }
}
// 2a. per-block reduce -> g_bsum
__global__ void scan_p1(int n) {
    int i = blockIdx.x * 1024 + threadIdx.x;
    int v = (i < n) ? g_counts[i] : 0;
    __shared__ int sw[32];
    int lane = threadIdx.x & 31, wid = threadIdx.x >> 5;
    int s = v;
    #pragma unroll
    for (int o = 16; o > 0; o >>= 1) s += __shfl_down_sync(0xffffffffu, s, o);
    if (lane == 0) sw[wid] = s;
    __syncthreads();
    if (wid == 0) {
        int t = sw[lane];
        #pragma unroll
        for (int o = 16; o > 0; o >>= 1) t += __shfl_down_sync(0xffffffffu, t, o);
        if (lane == 0) g_bsum[blockIdx.x] = t;
    }
}
// 2b. one block scans block sums
__global__ void scan_p2(int nb, int n) {
    int lane = threadIdx.x;  // 64 threads
    __shared__ int sm[64];
    int v = (lane < nb) ? g_bsum[lane] : 0;
    sm[lane] = v;
    __syncthreads();
    #pragma unroll
    for (int d = 1; d < 64; d <<= 1) {
        int t = (lane >= d) ? sm[lane - d] : 0;
        __syncthreads();
        sm[lane] += t;
        __syncthreads();
    }
    if (lane < nb) g_bsum[lane] = sm[lane] - v;
    if (lane == nb - 1) g_offs[n] = sm[lane];
}
// 2c. per-block inclusive scan + base -> offs/wptr/dis
__global__ void scan_p3(int n) {
    int base = g_bsum[blockIdx.x];
    int i = blockIdx.x * 1024 + threadIdx.x;
    int v = (i < n) ? g_counts[i] : 0;
    __shared__ int sw[32];
    int lane = threadIdx.x & 31, wid = threadIdx.x >> 5;
    int inc = v;
    #pragma unroll
    for (int o = 1; o < 32; o <<= 1) {
        int t = __shfl_up_sync(0xffffffffu, inc, o);
        if (lane >= o) inc += t;
    }
    if (lane == 31) sw[wid] = inc;
    __syncthreads();
    if (wid == 0) {
        int t = sw[lane];
        #pragma unroll
        for (int o = 1; o < 32; o <<= 1) {
            int u = __shfl_up_sync(0xffffffffu, t, o);
            if (lane >= o) t += u;
        }
        sw[lane] = t;
    }
    __syncthreads();
    int excl = base + inc - v + (wid > 0 ? sw[wid - 1] : 0);
    if (i < n) {
        g_offs[i] = excl;
        g_wptr[i] = excl;
        g_dis[i]  = rsqrtf(1.0f + (float)v);
    }
}
// 3. fill CSR
__global__ void fill_kernel(const int* __restrict__ ei, int E) {
    int e = blockIdx.x * blockDim.x + threadIdx.x;
    if (e < E) {
        int s = ei[e], d = ei[E + e];
        g_csr[atomicAdd(&g_wptr[d], 1)] = s;
    }
}

// ---------------------------------------------------------------------------
// 4. warp-per-node aggregation on fp16 rows -> fp16 out, node range [nlo, nhi)
template <int F>
__global__ void agg_f16(const __half* __restrict__ h, __half* __restrict__ oh,
                        int nlo, int nhi) {
    constexpr int HPL = F / 32;
    constexpr int W2L = HPL / 2;
    int node = nlo + blockIdx.x * (blockDim.x >> 5) + (threadIdx.x >> 5);
    int lane = threadIdx.x & 31;
    if (node >= nhi) return;

    float di = g_dis[node];
    float acc[HPL];
    {
        uint32_t v[W2L];
        if constexpr (F == 128) {
            uint2 u = ((const uint2*)(h + (size_t)node * F))[lane];
            v[0] = u.x; v[1] = u.y;
        } else {
            uint4 u = ((const uint4*)(h + (size_t)node * F))[lane];
            v[0] = u.x; v[1] = u.y; v[2] = u.z; v[3] = u.w;
        }
        #pragma unroll
        for (int q = 0; q < W2L; q++) {
            float2 f = __half22float2(*(__half2*)&v[q]);
            acc[2*q]   = di * f.x;
            acc[2*q+1] = di * f.y;
        }
    }
    int e0 = g_offs[node], e1 = g_offs[node + 1];
    for (int base = e0; base < e1; base += 32) {
        int e = base + lane;
        int s = 0; float w = 0.0f;
        if (e < e1) { s = g_csr[e]; w = g_dis[s]; }
        int cnt = min(32, e1 - base);
        #pragma unroll 4
        for (int j = 0; j < cnt; j++) {
            int   sj = __shfl_sync(0xffffffffu, s, j);
            float wj = __shfl_sync(0xffffffffu, w, j);
            uint32_t v[W2L];
            if constexpr (F == 128) {
                uint2 u = ((const uint2*)(h + (size_t)sj * F))[lane];
                v[0] = u.x; v[1] = u.y;
            } else {
                uint4 u = ((const uint4*)(h + (size_t)sj * F))[lane];
                v[0] = u.x; v[1] = u.y; v[2] = u.z; v[3] = u.w;
            }
            #pragma unroll
            for (int q = 0; q < W2L; q++) {
                float2 f = __half22float2(*(__half2*)&v[q]);
                acc[2*q]   += wj * f.x;
                acc[2*q+1] += wj * f.y;
            }
        }
    }
    uint32_t o[W2L];
    #pragma unroll
    for (int q = 0; q < W2L; q++) {
        __half2 hv = __floats2half2_rn(di * acc[2*q], di * acc[2*q+1]);
        o[q] = *(uint32_t*)&hv;
    }
    if constexpr (F == 128) {
        uint2 u; u.x = o[0]; u.y = o[1];
        ((uint2*)(oh + (size_t)node * F))[lane] = u;
    } else {
        uint4 u; u.x = o[0]; u.y = o[1]; u.z = o[2]; u.w = o[3];
        ((uint4*)(oh + (size_t)node * F))[lane] = u;
    }
}

// 5. all three weight transposes in one launch
__global__ void wtrans_all(const float* __restrict__ W1, const float* __restrict__ W2,
                           const float* __restrict__ W3, int K1) {
    int i = blockIdx.x * blockDim.x + threadIdx.x;
    int sz1 = K1 * 256, sz23 = 256 * 256;
    const float* W; __half* Wt; int idx, K;
    if (i < sz1)               { W = W1; Wt = g_W1t; idx = i;              K = K1;  }
    else if (i < sz1 + sz23)   { W = W2; Wt = g_W2t; idx = i - sz1;        K = 256; }
    else if (i < sz1 + 2*sz23) { W = W3; Wt = g_W3t; idx = i - sz1 - sz23; K = 256; }
    else return;
    int k = idx / 256, n = idx % 256;
    Wt[n * K + k] = __float2half_rn(W[idx]);
}

// ---------------------------------------------------------------------------
// 6. pure-fp16 tensor-core GEMM (R11 shape) with chunk row offset m_base.
#define PITCH_B 32
#define TILE_B  4096
#define SLAB_B  8192
#define STAGE_B (2 * SLAB_B)

template <bool POOL>
__global__ void __launch_bounds__(256)
gemm_tc(const __half* __restrict__ A, const __half* __restrict__ B,
        const float* __restrict__ bias, __half* __restrict__ C,
        const int* __restrict__ batch, int M, int K, int m_base) {
    extern __shared__ __align__(1024) char smem[];
    uint32_t sbase = smem_u32(smem);

    int tid = threadIdx.x;
    int wid = tid >> 5, lane = tid & 31;
    int wm = wid >> 2, wn = wid & 3;
    int m0 = m_base + blockIdx.y * 128, n0 = blockIdx.x * 128;

    float acc[4][4][4];
    #pragma unroll
    for (int i = 0; i < 4; i++)
        #pragma unroll
        for (int j = 0; j < 4; j++)
            #pragma unroll
            for (int q = 0; q < 4; q++) acc[i][j][q] = 0.0f;

    int npair = K >> 5;

    auto load_slab = [&](uint32_t sb, int k0) {
        #pragma unroll
        for (int i = 0; i < 2; i++) {
            int c = tid + i * 256;
            int tile = c >> 8, t = c & 255;
            int row = t >> 1, half = t & 1;
            uint32_t dst = sb + tile * TILE_B + row * PITCH_B +
                           ((half ^ ((row >> 2) & 1)) << 4);
            const __half* src;
            uint32_t sz = 16;
            if (tile == 0) {
                int gr = m0 + row;
                int cr = gr < M ? gr : (M - 1);
                src = A + (size_t)cr * K + k0 + half * 8;
                if (gr >= M) sz = 0;
            } else {
                src = B + (size_t)(n0 + row) * K + k0 + half * 8;
            }
            cp_async16(dst, src, sz);
        }
    };
    auto load_pair = [&](int stage, int p) {
        uint32_t sb = sbase + stage * STAGE_B;
        load_slab(sb,          p * 32);
        load_slab(sb + SLAB_B, p * 32 + 16);
        CP_COMMIT();
    };

    int r = lane & 15, sel = lane >> 4;

    auto compute_slab = [&](uint32_t sb) {
        uint32_t sA = sb, sB = sb + TILE_B;
        uint32_t af[4][4];
        #pragma unroll
        for (int mi = 0; mi < 4; mi++) {
            int rowA = wm * 64 + mi * 16 + r;
            uint32_t off = rowA * PITCH_B + ((sel ^ ((rowA >> 2) & 1)) << 4);
            ldsm_x4(af[mi][0], af[mi][1], af[mi][2], af[mi][3], sA + off);
        }
        uint32_t bf[2][4];
        #pragma unroll
        for (int nj = 0; nj < 2; nj++) {
            int rowB = wn * 32 + nj * 16 + r;
            uint32_t off = rowB * PITCH_B + ((sel ^ ((rowB >> 2) & 1)) << 4);
            ldsm_x4(bf[nj][0], bf[nj][1], bf[nj][2], bf[nj][3], sB + off);
        }
        #pragma unroll
        for (int mi = 0; mi < 4; mi++) {
            #pragma unroll
            for (int nn = 0; nn < 4; nn++) {
                int nj = nn >> 1, hi8 = nn & 1;
                mma_fp16(acc[mi][nn], af[mi], bf[nj][hi8], bf[nj][hi8 + 2]);
            }
        }
    };

    load_pair(0, 0);

    for (int p = 0; p < npair; p++) {
        if (p + 1 < npair) load_pair((p + 1) & 1, p + 1);
        if (p + 1 < npair) { CP_WAIT(1); } else { CP_WAIT(0); }
        __syncthreads();
        uint32_t sb = sbase + (p & 1) * STAGE_B;
        compute_slab(sb);
        compute_slab(sb + SLAB_B);
        __syncthreads();
    }

    // epilogue
    int qr = lane >> 2, qc = lane & 3;
    #pragma unroll
    for (int nn = 0; nn < 4; nn++) {
        int col = n0 + wn * 32 + (nn >> 1) * 16 + (nn & 1) * 8 + qc * 2;
        float bz0 = __ldg(&bias[col]), bz1 = __ldg(&bias[col + 1]);
        #pragma unroll
        for (int mi = 0; mi < 4; mi++) {
            int row0 = m0 + wm * 64 + mi * 16 + qr;
            if (row0 < M) {
                float v0 = fmaxf(acc[mi][nn][0] + bz0, 0.f);
                float v1 = fmaxf(acc[mi][nn][1] + bz1, 0.f);
                if (POOL) {
                    int g = __ldg(&batch[row0]);
                    atomicAdd(&g_sums[g * HID + col],     v0);
                    atomicAdd(&g_sums[g * HID + col + 1], v1);
                } else {
                    __half2 hv = __floats2half2_rn(v0, v1);
                    *(__half2*)(C + (size_t)row0 * 256 + col) = hv;
                }
            }
            int row1 = row0 + 8;
            if (row1 < M) {
                float v2 = fmaxf(acc[mi][nn][2] + bz0, 0.f);
                float v3 = fmaxf(acc[mi][nn][3] + bz1, 0.f);
                if (POOL) {
                    int g = __ldg(&batch[row1]);
                    atomicAdd(&g_sums[g * HID + col],     v2);
                    atomicAdd(&g_sums[g * HID + col + 1], v3);
                } else {
                    __half2 hv = __floats2half2_rn(v2, v3);
                    *(__half2*)(C + (size_t)row1 * 256 + col) = hv;
                }
            }
        }
    }
}

// ---------------------------------------------------------------------------
// 7. head: mean, concat, fc1(relu), fc2 -> out[G,16]
__global__ void head_kernel(const float* __restrict__ molwt, const float* __restrict__ nrings,
                            const float* __restrict__ fcW1, const float* __restrict__ fcb1,
                            const float* __restrict__ fcW2, const float* __restrict__ fcb2,
                            float* __restrict__ out) {
    int g = blockIdx.x;
    __shared__ float hg[258];
    __shared__ float h1[196];
    int t = threadIdx.x;  // 256
    float c = fmaxf((float)g_gcnt[g], 1.0f);
    hg[t] = g_sums[g * HID + t] / c;
    if (t == 0) { hg[256] = molwt[g]; hg[257] = nrings[g]; }
    __syncthreads();
    if (t < 196) {
        float a = fcb1[t];
        #pragma unroll 4
        for (int k = 0; k < 258; k++) a += hg[k] * fcW1[k * 196 + t];
        h1[t] = fmaxf(a, 0.0f);
    }
    __syncthreads();
    if (t < 16) {
        float a = fcb2[t];
        #pragma unroll 4
        for (int k = 0; k < 196; k++) a += h1[k] * fcW2[k * 16 + t];
        out[g * 16 + t] = a;
    }
}

// ---------------------------------------------------------------------------
extern "C" void kernel_launch(void* const* d_in, const int* in_sizes, int n_in,
                              void* d_out, int out_size) {
    const float* x      = (const float*)d_in[0];
    const int*   ei     = (const int*)  d_in[1];
    const int*   batch  = (const int*)  d_in[2];
    const float* molwt  = (const float*)d_in[3];
    const float* nrings = (const float*)d_in[4];
    const float* W1 = (const float*)d_in[5];
    const float* b1 = (const float*)d_in[6];
    const float* W2 = (const float*)d_in[7];
    const float* b2 = (const float*)d_in[8];
    const float* W3 = (const float*)d_in[9];
    const float* b3 = (const float*)d_in[10];
    const float* fcW1 = (const float*)d_in[11];
    const float* fcb1 = (const float*)d_in[12];
    const float* fcW2 = (const float*)d_in[13];
    const float* fcb2 = (const float*)d_in[14];

    const int N = in_sizes[2];
    const int E = in_sizes[1] / 2;
    const int G = in_sizes[3];
    const int F_IN = in_sizes[0] / N;   // 128

    __half *A, *H, *H2, *X16, *W1t, *W2t, *W3t;
    cudaGetSymbolAddress((void**)&A, g_A);
    cudaGetSymbolAddress((void**)&H, g_H);
    cudaGetSymbolAddress((void**)&H2, g_H2);
    cudaGetSymbolAddress((void**)&X16, g_x16);
    cudaGetSymbolAddress((void**)&W1t, g_W1t);
    cudaGetSymbolAddress((void**)&W2t, g_W2t);
    cudaGetSymbolAddress((void**)&W3t, g_W3t);

    const int GEMM_SMEM = 2 * STAGE_B;   // 32768
    cudaFuncSetAttribute(gemm_tc<false>, cudaFuncAttributeMaxDynamicSharedMemorySize, GEMM_SMEM);
    cudaFuncSetAttribute(gemm_tc<true >, cudaFuncAttributeMaxDynamicSharedMemorySize, GEMM_SMEM);

    int nb = (N + 1023) / 1024;

    // chunking: 4 row-chunks, 128-aligned
    int cbase[4], ctiles[4], cn[4];
    for (int c = 0; c < 4; c++) {
        cbase[c] = c * CHUNK_ROWS;
        int hi = min(cbase[c] + CHUNK_ROWS, N);
        cn[c] = (hi > cbase[c]) ? (hi - cbase[c]) : 0;
        ctiles[c] = (cn[c] + 127) / 128;
    }

    // setup (capture stream)
    init_kernel<<<256, 256>>>(N, G);
    count_gcnt<<<(E + N + 255) / 256, 256>>>(ei, batch, E, N);
    xhalf_kernel<<<(N * F_IN / 4 + 255) / 256, 256>>>(x, X16, N * F_IN / 4);
    scan_p1<<<nb, 1024>>>(N);
    scan_p2<<<1, 64>>>(nb, N);
    scan_p3<<<nb, 1024>>>(N);
    fill_kernel<<<(E + 255) / 256, 256>>>(ei, E);
    int wtot = F_IN * 256 + 2 * 256 * 256;
    wtrans_all<<<(wtot + 255) / 256, 256>>>(W1, W2, W3, F_IN);

    // per-layer chunked overlap: agg on capture stream, gemm on s2.
    // IMPORTANT: layer input and gemm output are always DIFFERENT buffers
    // (X16->H, H->H2, H2->pool) so concurrent chunks never race.
    auto run_layer = [&](int l, const __half* Hin, int F, const __half* Wt,
                         const float* bias, __half* Cout, bool pool) {
        for (int c = 0; c < 4; c++) {
            if (cn[c] <= 0) continue;
            int blocks = (cn[c] + 7) / 8;
            if (F == 128) agg_f16<128><<<blocks, 256>>>(Hin, A, cbase[c], cbase[c] + cn[c]);
            else          agg_f16<256><<<blocks, 256>>>(Hin, A, cbase[c], cbase[c] + cn[c]);
            cudaEventRecord(g_sp.evA[l * 4 + c], 0);
        }
        for (int c = 0; c < 4; c++) {
            if (cn[c] <= 0) continue;
            cudaStreamWaitEvent(g_sp.s2, g_sp.evA[l * 4 + c], 0);
            dim3 gg(2, ctiles[c]);
            if (pool)
                gemm_tc<true ><<<gg, 256, GEMM_SMEM, g_sp.s2>>>(A, Wt, bias, nullptr, batch, N, F, cbase[c]);
            else
                gemm_tc<false><<<gg, 256, GEMM_SMEM, g_sp.s2>>>(A, Wt, bias, Cout, nullptr, N, F, cbase[c]);
        }
        cudaEventRecord(g_sp.evJ[l], g_sp.s2);
        cudaStreamWaitEvent(0, g_sp.evJ[l], 0);
    };

    run_layer(0, X16, 128, W1t, b1, H,  false);   // x -> H
    run_layer(1, H,   256, W2t, b2, H2, false);   // H -> H2
    run_layer(2, H2,  256, W3t, b3, nullptr, true); // H2 -> pooled g_sums

    // head
    head_kernel<<<G, 256>>>(molwt, nrings, fcW1, fcb1, fcW2, fcb2, (float*)d_out);
}

// round 14
// speedup vs baseline: 1.2099x; 1.2099x over previous
#include <cuda_runtime.h>
#include <cuda_fp16.h>
#include <cstdint>
#include <math.h>

// Problem constants (fixed for this dataset)
#define MAXN 50000
#define MAXE 800000
#define MAXG 512
#define HID  256

// ---------------------------------------------------------------------------
// Scratch (__device__ globals: allocation-free per harness rules)
__device__ __half g_A[(size_t)MAXN * HID];            // agg output, fp16
__device__ __half g_H[(size_t)MAXN * HID];            // hidden state, fp16
__device__ __half g_x16[(size_t)MAXN * 128];          // fp16 copy of input x
__device__ float g_dis[MAXN];
__device__ int   g_counts[MAXN];
__device__ int   g_offs[MAXN + 1];
__device__ int   g_wptr[MAXN];
__device__ int2  g_csr2[MAXE];                        // {src, bits(dis[src])}
__device__ float g_sums[MAXG * HID];
__device__ int   g_gcnt[MAXG];
__device__ int   g_bsum[64];
// transposed weights: [N=256 rows][K cols], K-major fp16
__device__ __half g_W1t[256 * 128];
__device__ __half g_W2t[256 * 256];
__device__ __half g_W3t[256 * 256];

// ---------------------------------------------------------------------------
// base-ISA tensor helpers (mma.sync / ldmatrix / cp.async)
__device__ __forceinline__ void ldsm_x4(uint32_t& r0, uint32_t& r1, uint32_t& r2, uint32_t& r3,
                                        uint32_t addr) {
    asm volatile("ldmatrix.sync.aligned.m8n8.x4.shared.b16 {%0,%1,%2,%3}, [%4];"
                 : "=r"(r0), "=r"(r1), "=r"(r2), "=r"(r3) : "r"(addr));
}
__device__ __forceinline__ void mma_fp16(float* c, const uint32_t* a, uint32_t b0, uint32_t b1) {
    asm volatile("mma.sync.aligned.m16n8k16.row.col.f32.f16.f16.f32 "
                 "{%0,%1,%2,%3}, {%4,%5,%6,%7}, {%8,%9}, {%0,%1,%2,%3};"
                 : "+f"(c[0]), "+f"(c[1]), "+f"(c[2]), "+f"(c[3])
                 : "r"(a[0]), "r"(a[1]), "r"(a[2]), "r"(a[3]), "r"(b0), "r"(b1));
}
__device__ __forceinline__ void cp_async16(uint32_t smem_addr, const void* gptr, uint32_t src_sz) {
    asm volatile("cp.async.cg.shared.global [%0], [%1], 16, %2;"
                 :: "r"(smem_addr), "l"(gptr), "r"(src_sz) : "memory");
}
#define CP_COMMIT() asm volatile("cp.async.commit_group;" ::: "memory")
#define CP_WAIT(n)  asm volatile("cp.async.wait_group %0;" :: "n"(n) : "memory")
__device__ __forceinline__ uint32_t smem_u32(const void* p) {
    uint32_t a;
    asm("{ .reg .u64 t; cvta.to.shared.u64 t, %1; cvt.u32.u64 %0, t; }" : "=r"(a) : "l"(p));
    return a;
}

// ---------------------------------------------------------------------------
// 0. zero-init
__global__ void init_kernel(int n_nodes, int n_graphs) {
    int i = blockIdx.x * blockDim.x + threadIdx.x;
    int total = n_nodes + n_graphs + n_graphs * HID;
    for (; i < total; i += gridDim.x * blockDim.x) {
        if (i < n_nodes) g_counts[i] = 0;
        else if (i < n_nodes + n_graphs) g_gcnt[i - n_nodes] = 0;
        else g_sums[i - n_nodes - n_graphs] = 0.0f;
    }
}
// 1. merged setup: degree counts + graph counts + x->fp16 + weight transposes
__global__ void setup_kernel(const int* __restrict__ ei, const int* __restrict__ batch,
                             const float* __restrict__ x, __half* __restrict__ x16,
                             const float* __restrict__ W1, const float* __restrict__ W2,
                             const float* __restrict__ W3,
                             int E, int N, int K1) {
    int i = blockIdx.x * blockDim.x + threadIdx.x;
    if (i < E) { atomicAdd(&g_counts[ei[E + i]], 1); return; }
    i -= E;
    if (i < N) { atomicAdd(&g_gcnt[batch[i]], 1); return; }
    i -= N;
    int x4 = N * K1 / 4;
    if (i < x4) {                       // x -> fp16, 4 elems/thread
        float4 f = ((const float4*)x)[i];
        __half2 a = __floats2half2_rn(f.x, f.y);
        __half2 b = __floats2half2_rn(f.z, f.w);
        uint2 u; u.x = *(uint32_t*)&a; u.y = *(uint32_t*)&b;
        ((uint2*)x16)[i] = u;
        return;
    }
    i -= x4;
    int sz1 = K1 * 256, sz23 = 256 * 256;
    const float* W; __half* Wt; int idx, K;
    if (i < sz1)               { W = W1; Wt = g_W1t; idx = i;              K = K1;  }
    else if (i < sz1 + sz23)   { W = W2; Wt = g_W2t; idx = i - sz1;        K = 256; }
    else if (i < sz1 + 2*sz23) { W = W3; Wt = g_W3t; idx = i - sz1 - sz23; K = 256; }
    else return;
    int k = idx / 256, n = idx % 256;
    Wt[n * K + k] = __float2half_rn(W[idx]);
}
// 2a. per-block reduce -> g_bsum
__global__ void scan_p1(int n) {
    int i = blockIdx.x * 1024 + threadIdx.x;
    int v = (i < n) ? g_counts[i] : 0;
    __shared__ int sw[32];
    int lane = threadIdx.x & 31, wid = threadIdx.x >> 5;
    int s = v;
    #pragma unroll
    for (int o = 16; o > 0; o >>= 1) s += __shfl_down_sync(0xffffffffu, s, o);
    if (lane == 0) sw[wid] = s;
    __syncthreads();
    if (wid == 0) {
        int t = sw[lane];
        #pragma unroll
        for (int o = 16; o > 0; o >>= 1) t += __shfl_down_sync(0xffffffffu, t, o);
        if (lane == 0) g_bsum[blockIdx.x] = t;
    }
}
// 2b. one block scans block sums
__global__ void scan_p2(int nb, int n) {
    int lane = threadIdx.x;  // 64 threads
    __shared__ int sm[64];
    int v = (lane < nb) ? g_bsum[lane] : 0;
    sm[lane] = v;
    __syncthreads();
    #pragma unroll
    for (int d = 1; d < 64; d <<= 1) {
        int t = (lane >= d) ? sm[lane - d] : 0;
        __syncthreads();
        sm[lane] += t;
        __syncthreads();
    }
    if (lane < nb) g_bsum[lane] = sm[lane] - v;
    if (lane == nb - 1) g_offs[n] = sm[lane];
}
// 2c. per-block inclusive scan + base -> offs/wptr/dis
__global__ void scan_p3(int n) {
    int base = g_bsum[blockIdx.x];
    int i = blockIdx.x * 1024 + threadIdx.x;
    int v = (i < n) ? g_counts[i] : 0;
    __shared__ int sw[32];
    int lane = threadIdx.x & 31, wid = threadIdx.x >> 5;
    int inc = v;
    #pragma unroll
    for (int o = 1; o < 32; o <<= 1) {
        int t = __shfl_up_sync(0xffffffffu, inc, o);
        if (lane >= o) inc += t;
    }
    if (lane == 31) sw[wid] = inc;
    __syncthreads();
    if (wid == 0) {
        int t = sw[lane];
        #pragma unroll
        for (int o = 1; o < 32; o <<= 1) {
            int u = __shfl_up_sync(0xffffffffu, t, o);
            if (lane >= o) t += u;
        }
        sw[lane] = t;
    }
    __syncthreads();
    int excl = base + inc - v + (wid > 0 ? sw[wid - 1] : 0);
    if (i < n) {
        g_offs[i] = excl;
        g_wptr[i] = excl;
        g_dis[i]  = rsqrtf(1.0f + (float)v);
    }
}
// 3. fill CSR with packed {src, dis[src]} pairs (dis ready after scan_p3)
__global__ void fill_kernel(const int* __restrict__ ei, int E) {
    int e = blockIdx.x * blockDim.x + threadIdx.x;
    if (e < E) {
        int s = ei[e], d = ei[E + e];
        int p = atomicAdd(&g_wptr[d], 1);
        g_csr2[p] = make_int2(s, __float_as_int(g_dis[s]));
    }
}

// ---------------------------------------------------------------------------
// 4. warp-per-node aggregation on fp16 rows -> fp16 out. F in {128, 256}.
//    Edge scan reads packed (src, w) in one 8B load.
template <int F>
__global__ void agg_f16(const __half* __restrict__ h, __half* __restrict__ oh, int N) {
    constexpr int HPL = F / 32;
    constexpr int W2L = HPL / 2;
    int node = blockIdx.x * (blockDim.x >> 5) + (threadIdx.x >> 5);
    int lane = threadIdx.x & 31;
    if (node >= N) return;

    float di = g_dis[node];
    float acc[HPL];
    {
        uint32_t v[W2L];
        if constexpr (F == 128) {
            uint2 u = ((const uint2*)(h + (size_t)node * F))[lane];
            v[0] = u.x; v[1] = u.y;
        } else {
            uint4 u = ((const uint4*)(h + (size_t)node * F))[lane];
            v[0] = u.x; v[1] = u.y; v[2] = u.z; v[3] = u.w;
        }
        #pragma unroll
        for (int q = 0; q < W2L; q++) {
            float2 f = __half22float2(*(__half2*)&v[q]);
            acc[2*q]   = di * f.x;
            acc[2*q+1] = di * f.y;
        }
    }
    int e0 = g_offs[node], e1 = g_offs[node + 1];
    for (int base = e0; base < e1; base += 32) {
        int e = base + lane;
        int s = 0; float w = 0.0f;
        if (e < e1) { int2 p = g_csr2[e]; s = p.x; w = __int_as_float(p.y); }
        int cnt = min(32, e1 - base);
        #pragma unroll 4
        for (int j = 0; j < cnt; j++) {
            int   sj = __shfl_sync(0xffffffffu, s, j);
            float wj = __shfl_sync(0xffffffffu, w, j);
            uint32_t v[W2L];
            if constexpr (F == 128) {
                uint2 u = ((const uint2*)(h + (size_t)sj * F))[lane];
                v[0] = u.x; v[1] = u.y;
            } else {
                uint4 u = ((const uint4*)(h + (size_t)sj * F))[lane];
                v[0] = u.x; v[1] = u.y; v[2] = u.z; v[3] = u.w;
            }
            #pragma unroll
            for (int q = 0; q < W2L; q++) {
                float2 f = __half22float2(*(__half2*)&v[q]);
                acc[2*q]   += wj * f.x;
                acc[2*q+1] += wj * f.y;
            }
        }
    }
    uint32_t o[W2L];
    #pragma unroll
    for (int q = 0; q < W2L; q++) {
        __half2 hv = __floats2half2_rn(di * acc[2*q], di * acc[2*q+1]);
        o[q] = *(uint32_t*)&hv;
    }
    if constexpr (F == 128) {
        uint2 u; u.x = o[0]; u.y = o[1];
        ((uint2*)(oh + (size_t)node * F))[lane] = u;
    } else {
        uint4 u; u.x = o[0]; u.y = o[1]; u.z = o[2]; u.w = o[3];
        ((uint4*)(oh + (size_t)node * F))[lane] = u;
    }
}

// ---------------------------------------------------------------------------
// 5. pure-fp16 tensor-core GEMM (R11 shape): C = relu( A @ B^T + bias ).
//    CTA 128x128, 256 thr, paired k16 slabs per stage (k=32), double buffer.
#define PITCH_B 32
#define TILE_B  4096
#define SLAB_B  8192             // one k16 slab: A, B tiles
#define STAGE_B (2 * SLAB_B)

template <bool POOL>
__global__ void __launch_bounds__(256)
gemm_tc(const __half* __restrict__ A, const __half* __restrict__ B,
        const float* __restrict__ bias, __half* __restrict__ C,
        const int* __restrict__ batch, int M, int K) {
    extern __shared__ __align__(1024) char smem[];
    uint32_t sbase = smem_u32(smem);

    int tid = threadIdx.x;
    int wid = tid >> 5, lane = tid & 31;
    int wm = wid >> 2, wn = wid & 3;
    int m0 = blockIdx.y * 128, n0 = blockIdx.x * 128;

    float acc[4][4][4];
    #pragma unroll
    for (int i = 0; i < 4; i++)
        #pragma unroll
        for (int j = 0; j < 4; j++)
            #pragma unroll
            for (int q = 0; q < 4; q++) acc[i][j][q] = 0.0f;

    int npair = K >> 5;

    auto load_slab = [&](uint32_t sb, int k0) {
        #pragma unroll
        for (int i = 0; i < 2; i++) {
            int c = tid + i * 256;
            int tile = c >> 8, t = c & 255;
            int row = t >> 1, half = t & 1;
            uint32_t dst = sb + tile * TILE_B + row * PITCH_B +
                           ((half ^ ((row >> 2) & 1)) << 4);
            const __half* src;
            uint32_t sz = 16;
            if (tile == 0) {
                int gr = m0 + row;
                int cr = gr < M ? gr : (M - 1);
                src = A + (size_t)cr * K + k0 + half * 8;
                if (gr >= M) sz = 0;
            } else {
                src = B + (size_t)(n0 + row) * K + k0 + half * 8;
            }
            cp_async16(dst, src, sz);
        }
    };
    auto load_pair = [&](int stage, int p) {
        uint32_t sb = sbase + stage * STAGE_B;
        load_slab(sb,          p * 32);
        load_slab(sb + SLAB_B, p * 32 + 16);
        CP_COMMIT();
    };

    int r = lane & 15, sel = lane >> 4;

    auto compute_slab = [&](uint32_t sb) {
        uint32_t sA = sb, sB = sb + TILE_B;
        uint32_t af[4][4];
        #pragma unroll
        for (int mi = 0; mi < 4; mi++) {
            int rowA = wm * 64 + mi * 16 + r;
            uint32_t off = rowA * PITCH_B + ((sel ^ ((rowA >> 2) & 1)) << 4);
            ldsm_x4(af[mi][0], af[mi][1], af[mi][2], af[mi][3], sA + off);
        }
        uint32_t bf[2][4];
        #pragma unroll
        for (int nj = 0; nj < 2; nj++) {
            int rowB = wn * 32 + nj * 16 + r;
            uint32_t off = rowB * PITCH_B + ((sel ^ ((rowB >> 2) & 1)) << 4);
            ldsm_x4(bf[nj][0], bf[nj][1], bf[nj][2], bf[nj][3], sB + off);
        }
        #pragma unroll
        for (int mi = 0; mi < 4; mi++) {
            #pragma unroll
            for (int nn = 0; nn < 4; nn++) {
                int nj = nn >> 1, hi8 = nn & 1;
                mma_fp16(acc[mi][nn], af[mi], bf[nj][hi8], bf[nj][hi8 + 2]);
            }
        }
    };

    load_pair(0, 0);

    for (int p = 0; p < npair; p++) {
        if (p + 1 < npair) load_pair((p + 1) & 1, p + 1);
        if (p + 1 < npair) { CP_WAIT(1); } else { CP_WAIT(0); }
        __syncthreads();
        uint32_t sb = sbase + (p & 1) * STAGE_B;
        compute_slab(sb);
        compute_slab(sb + SLAB_B);
        __syncthreads();
    }

    // epilogue
    int qr = lane >> 2, qc = lane & 3;
    #pragma unroll
    for (int nn = 0; nn < 4; nn++) {
        int col = n0 + wn * 32 + (nn >> 1) * 16 + (nn & 1) * 8 + qc * 2;
        float bz0 = __ldg(&bias[col]), bz1 = __ldg(&bias[col + 1]);
        #pragma unroll
        for (int mi = 0; mi < 4; mi++) {
            int row0 = m0 + wm * 64 + mi * 16 + qr;
            if (row0 < M) {
                float v0 = fmaxf(acc[mi][nn][0] + bz0, 0.f);
                float v1 = fmaxf(acc[mi][nn][1] + bz1, 0.f);
                if (POOL) {
                    int g = __ldg(&batch[row0]);
                    atomicAdd(&g_sums[g * HID + col],     v0);
                    atomicAdd(&g_sums[g * HID + col + 1], v1);
                } else {
                    __half2 hv = __floats2half2_rn(v0, v1);
                    *(__half2*)(C + (size_t)row0 * 256 + col) = hv;
                }
            }
            int row1 = row0 + 8;
            if (row1 < M) {
                float v2 = fmaxf(acc[mi][nn][2] + bz0, 0.f);
                float v3 = fmaxf(acc[mi][nn][3] + bz1, 0.f);
                if (POOL) {
                    int g = __ldg(&batch[row1]);
                    atomicAdd(&g_sums[g * HID + col],     v2);
                    atomicAdd(&g_sums[g * HID + col + 1], v3);
                } else {
                    __half2 hv = __floats2half2_rn(v2, v3);
                    *(__half2*)(C + (size_t)row1 * 256 + col) = hv;
                }
            }
        }
    }
}

// ---------------------------------------------------------------------------
// 6. head: mean, concat, fc1(relu), fc2 -> out[G,16]
__global__ void head_kernel(const float* __restrict__ molwt, const float* __restrict__ nrings,
                            const float* __restrict__ fcW1, const float* __restrict__ fcb1,
                            const float* __restrict__ fcW2, const float* __restrict__ fcb2,
                            float* __restrict__ out) {
    int g = blockIdx.x;
    __shared__ float hg[258];
    __shared__ float h1[196];
    int t = threadIdx.x;  // 256
    float c = fmaxf((float)g_gcnt[g], 1.0f);
    hg[t] = g_sums[g * HID + t] / c;
    if (t == 0) { hg[256] = molwt[g]; hg[257] = nrings[g]; }
    __syncthreads();
    if (t < 196) {
        float a = fcb1[t];
        #pragma unroll 4
        for (int k = 0; k < 258; k++) a += hg[k] * fcW1[k * 196 + t];
        h1[t] = fmaxf(a, 0.0f);
    }
    __syncthreads();
    if (t < 16) {
        float a = fcb2[t];
        #pragma unroll 4
        for (int k = 0; k < 196; k++) a += h1[k] * fcW2[k * 16 + t];
        out[g * 16 + t] = a;
    }
}

// ---------------------------------------------------------------------------
extern "C" void kernel_launch(void* const* d_in, const int* in_sizes, int n_in,
                              void* d_out, int out_size) {
    const float* x      = (const float*)d_in[0];
    const int*   ei     = (const int*)  d_in[1];
    const int*   batch  = (const int*)  d_in[2];
    const float* molwt  = (const float*)d_in[3];
    const float* nrings = (const float*)d_in[4];
    const float* W1 = (const float*)d_in[5];
    const float* b1 = (const float*)d_in[6];
    const float* W2 = (const float*)d_in[7];
    const float* b2 = (const float*)d_in[8];
    const float* W3 = (const float*)d_in[9];
    const float* b3 = (const float*)d_in[10];
    const float* fcW1 = (const float*)d_in[11];
    const float* fcb1 = (const float*)d_in[12];
    const float* fcW2 = (const float*)d_in[13];
    const float* fcb2 = (const float*)d_in[14];

    const int N = in_sizes[2];
    const int E = in_sizes[1] / 2;
    const int G = in_sizes[3];
    const int F_IN = in_sizes[0] / N;   // 128

    __half *A, *H, *X16, *W1t, *W2t, *W3t;
    cudaGetSymbolAddress((void**)&A, g_A);
    cudaGetSymbolAddress((void**)&H, g_H);
    cudaGetSymbolAddress((void**)&X16, g_x16);
    cudaGetSymbolAddress((void**)&W1t, g_W1t);
    cudaGetSymbolAddress((void**)&W2t, g_W2t);
    cudaGetSymbolAddress((void**)&W3t, g_W3t);

    const int GEMM_SMEM = 2 * STAGE_B;   // 32768
    cudaFuncSetAttribute(gemm_tc<false>, cudaFuncAttributeMaxDynamicSharedMemorySize, GEMM_SMEM);
    cudaFuncSetAttribute(gemm_tc<true >, cudaFuncAttributeMaxDynamicSharedMemorySize, GEMM_SMEM);

    int nb = (N + 1023) / 1024;
    dim3 ggrid(2, (N + 127) / 128);
    int aggblocks = (N + 7) / 8;   // 8 warps / block

    // setup
    init_kernel<<<256, 256>>>(N, G);
    int stot = E + N + N * F_IN / 4 + F_IN * 256 + 2 * 256 * 256;
    setup_kernel<<<(stot + 255) / 256, 256>>>(ei, batch, x, X16, W1, W2, W3, E, N, F_IN);
    scan_p1<<<nb, 1024>>>(N);
    scan_p2<<<1, 64>>>(nb, N);
    scan_p3<<<nb, 1024>>>(N);
    fill_kernel<<<(E + 255) / 256, 256>>>(ei, E);

    // layer 1: fp16 x -> A, GEMM -> H
    agg_f16<128><<<aggblocks, 256>>>(X16, A, N);
    gemm_tc<false><<<ggrid, 256, GEMM_SMEM>>>(A, W1t, b1, H, nullptr, N, F_IN);
    // layer 2
    agg_f16<256><<<aggblocks, 256>>>(H, A, N);
    gemm_tc<false><<<ggrid, 256, GEMM_SMEM>>>(A, W2t, b2, H, nullptr, N, HID);
    // layer 3 (pooling fused into epilogue)
    agg_f16<256><<<aggblocks, 256>>>(H, A, N);
    gemm_tc<true><<<ggrid, 256, GEMM_SMEM>>>(A, W3t, b3, nullptr, batch, N, HID);

    // head
    head_kernel<<<G, 256>>>(molwt, nrings, fcW1, fcb1, fcW2, fcb2, (float*)d_out);
}

// round 15
// speedup vs baseline: 1.2287x; 1.0155x over previous
#include <cuda_runtime.h>
#include <cuda_fp16.h>
#include <cstdint>
#include <math.h>

// Problem constants (fixed for this dataset)
#define MAXN 50000
#define MAXE 800000
#define MAXG 512
#define HID  256

// ---------------------------------------------------------------------------
// Scratch (__device__ globals: allocation-free per harness rules)
__device__ __half g_A[(size_t)MAXN * HID];            // agg output, fp16
__device__ __half g_H[(size_t)MAXN * HID];            // hidden state, fp16
__device__ __half g_x16[(size_t)MAXN * 128];          // fp16 copy of input x
__device__ float g_dis[MAXN];
__device__ int   g_counts[MAXN];
__device__ int   g_offs[MAXN + 1];
__device__ int   g_wptr[MAXN];
__device__ int2  g_csr2[MAXE];                        // {src, bits(dis[src])}
__device__ float g_sums[MAXG * HID];
__device__ int   g_gcnt[MAXG];
__device__ int   g_bsum[64];
__device__ int   g_tick;                              // scan ticket (self-resets)
// transposed weights: [N=256 rows][K cols], K-major fp16
__device__ __half g_W1t[256 * 128];
__device__ __half g_W2t[256 * 256];
__device__ __half g_W3t[256 * 256];

// ---------------------------------------------------------------------------
// base-ISA tensor helpers (mma.sync / ldmatrix / cp.async)
__device__ __forceinline__ void ldsm_x4(uint32_t& r0, uint32_t& r1, uint32_t& r2, uint32_t& r3,
                                        uint32_t addr) {
    asm volatile("ldmatrix.sync.aligned.m8n8.x4.shared.b16 {%0,%1,%2,%3}, [%4];"
                 : "=r"(r0), "=r"(r1), "=r"(r2), "=r"(r3) : "r"(addr));
}
__device__ __forceinline__ void mma_fp16(float* c, const uint32_t* a, uint32_t b0, uint32_t b1) {
    asm volatile("mma.sync.aligned.m16n8k16.row.col.f32.f16.f16.f32 "
                 "{%0,%1,%2,%3}, {%4,%5,%6,%7}, {%8,%9}, {%0,%1,%2,%3};"
                 : "+f"(c[0]), "+f"(c[1]), "+f"(c[2]), "+f"(c[3])
                 : "r"(a[0]), "r"(a[1]), "r"(a[2]), "r"(a[3]), "r"(b0), "r"(b1));
}
__device__ __forceinline__ void cp_async16(uint32_t smem_addr, const void* gptr, uint32_t src_sz) {
    asm volatile("cp.async.cg.shared.global [%0], [%1], 16, %2;"
                 :: "r"(smem_addr), "l"(gptr), "r"(src_sz) : "memory");
}
#define CP_COMMIT() asm volatile("cp.async.commit_group;" ::: "memory")
#define CP_WAIT(n)  asm volatile("cp.async.wait_group %0;" :: "n"(n) : "memory")
__device__ __forceinline__ uint32_t smem_u32(const void* p) {
    uint32_t a;
    asm("{ .reg .u64 t; cvta.to.shared.u64 t, %1; cvt.u32.u64 %0, t; }" : "=r"(a) : "l"(p));
    return a;
}

// ---------------------------------------------------------------------------
// 0. zero-init
__global__ void init_kernel(int n_nodes, int n_graphs) {
    int i = blockIdx.x * blockDim.x + threadIdx.x;
    int total = n_nodes + n_graphs + n_graphs * HID;
    for (; i < total; i += gridDim.x * blockDim.x) {
        if (i < n_nodes) g_counts[i] = 0;
        else if (i < n_nodes + n_graphs) g_gcnt[i - n_nodes] = 0;
        else g_sums[i - n_nodes - n_graphs] = 0.0f;
    }
}
// 1. merged setup: degree counts + graph counts + x->fp16 + weight transposes
__global__ void setup_kernel(const int* __restrict__ ei, const int* __restrict__ batch,
                             const float* __restrict__ x, __half* __restrict__ x16,
                             const float* __restrict__ W1, const float* __restrict__ W2,
                             const float* __restrict__ W3,
                             int E, int N, int K1) {
    int i = blockIdx.x * blockDim.x + threadIdx.x;
    if (i < E) { atomicAdd(&g_counts[ei[E + i]], 1); return; }
    i -= E;
    if (i < N) { atomicAdd(&g_gcnt[batch[i]], 1); return; }
    i -= N;
    int x4 = N * K1 / 4;
    if (i < x4) {
        float4 f = ((const float4*)x)[i];
        __half2 a = __floats2half2_rn(f.x, f.y);
        __half2 b = __floats2half2_rn(f.z, f.w);
        uint2 u; u.x = *(uint32_t*)&a; u.y = *(uint32_t*)&b;
        ((uint2*)x16)[i] = u;
        return;
    }
    i -= x4;
    int sz1 = K1 * 256, sz23 = 256 * 256;
    const float* W; __half* Wt; int idx, K;
    if (i < sz1)               { W = W1; Wt = g_W1t; idx = i;              K = K1;  }
    else if (i < sz1 + sz23)   { W = W2; Wt = g_W2t; idx = i - sz1;        K = 256; }
    else if (i < sz1 + 2*sz23) { W = W3; Wt = g_W3t; idx = i - sz1 - sz23; K = 256; }
    else return;
    int k = idx / 256, n = idx % 256;
    Wt[n * K + k] = __float2half_rn(W[idx]);
}
// 2a. fused per-block reduce + (last block) scan of block sums.
//     Ticket self-resets so every call starts from g_tick == 0.
__global__ void scan_p12(int n, int nb) {
    int i = blockIdx.x * 1024 + threadIdx.x;
    int v = (i < n) ? g_counts[i] : 0;
    __shared__ int sw[32];
    __shared__ int isLast;
    int lane = threadIdx.x & 31, wid = threadIdx.x >> 5;
    int s = v;
    #pragma unroll
    for (int o = 16; o > 0; o >>= 1) s += __shfl_down_sync(0xffffffffu, s, o);
    if (lane == 0) sw[wid] = s;
    __syncthreads();
    if (wid == 0) {
        int t = sw[lane];
        #pragma unroll
        for (int o = 16; o > 0; o >>= 1) t += __shfl_down_sync(0xffffffffu, t, o);
        if (lane == 0) g_bsum[blockIdx.x] = t;
    }
    // ticket: last block to arrive scans the block sums
    if (threadIdx.x == 0) {
        __threadfence();
        isLast = (atomicAdd(&g_tick, 1) == nb - 1);
    }
    __syncthreads();
    if (isLast && wid == 1) {       // one warp (64 needs 2 rounds; nb <= 49 so 1 warp x2)
        if (lane == 0) g_tick = 0;  // reset for next call
        // sequential-ish exclusive scan of nb (<=64) entries by 32 lanes
        // load two entries per lane, do a simple shared scan
        __shared__ int sm[64];
        sm[lane] = (lane < nb) ? g_bsum[lane] : 0;
        sm[lane + 32] = (lane + 32 < nb) ? g_bsum[lane + 32] : 0;
        __syncwarp();
        // serial scan by lane 0 (nb <= 49, trivial)
        if (lane == 0) {
            int run = 0;
            for (int b = 0; b < nb; b++) {
                int t = sm[b];
                g_bsum[b] = run;
                run += t;
            }
            g_offs[n] = run;
            __threadfence();
        }
    }
}
// 2c. per-block inclusive scan + base -> offs/wptr/dis
__global__ void scan_p3(int n) {
    int base = g_bsum[blockIdx.x];
    int i = blockIdx.x * 1024 + threadIdx.x;
    int v = (i < n) ? g_counts[i] : 0;
    __shared__ int sw[32];
    int lane = threadIdx.x & 31, wid = threadIdx.x >> 5;
    int inc = v;
    #pragma unroll
    for (int o = 1; o < 32; o <<= 1) {
        int t = __shfl_up_sync(0xffffffffu, inc, o);
        if (lane >= o) inc += t;
    }
    if (lane == 31) sw[wid] = inc;
    __syncthreads();
    if (wid == 0) {
        int t = sw[lane];
        #pragma unroll
        for (int o = 1; o < 32; o <<= 1) {
            int u = __shfl_up_sync(0xffffffffu, t, o);
            if (lane >= o) t += u;
        }
        sw[lane] = t;
    }
    __syncthreads();
    int excl = base + inc - v + (wid > 0 ? sw[wid - 1] : 0);
    if (i < n) {
        g_offs[i] = excl;
        g_wptr[i] = excl;
        g_dis[i]  = rsqrtf(1.0f + (float)v);
    }
}
// 3. fill CSR with packed {src, dis[src]} pairs
__global__ void fill_kernel(const int* __restrict__ ei, int E) {
    int e = blockIdx.x * blockDim.x + threadIdx.x;
    if (e < E) {
        int s = ei[e], d = ei[E + e];
        int p = atomicAdd(&g_wptr[d], 1);
        g_csr2[p] = make_int2(s, __float_as_int(g_dis[s]));
    }
}

// ---------------------------------------------------------------------------
// 4. warp-per-node aggregation on fp16 rows -> fp16 out. F in {128, 256}.
template <int F>
__global__ void agg_f16(const __half* __restrict__ h, __half* __restrict__ oh, int N) {
    constexpr int HPL = F / 32;
    constexpr int W2L = HPL / 2;
    int node = blockIdx.x * (blockDim.x >> 5) + (threadIdx.x >> 5);
    int lane = threadIdx.x & 31;
    if (node >= N) return;

    float di = g_dis[node];
    float acc[HPL];
    {
        uint32_t v[W2L];
        if constexpr (F == 128) {
            uint2 u = ((const uint2*)(h + (size_t)node * F))[lane];
            v[0] = u.x; v[1] = u.y;
        } else {
            uint4 u = ((const uint4*)(h + (size_t)node * F))[lane];
            v[0] = u.x; v[1] = u.y; v[2] = u.z; v[3] = u.w;
        }
        #pragma unroll
        for (int q = 0; q < W2L; q++) {
            float2 f = __half22float2(*(__half2*)&v[q]);
            acc[2*q]   = di * f.x;
            acc[2*q+1] = di * f.y;
        }
    }
    int e0 = g_offs[node], e1 = g_offs[node + 1];
    for (int base = e0; base < e1; base += 32) {
        int e = base + lane;
        int s = 0; float w = 0.0f;
        if (e < e1) { int2 p = g_csr2[e]; s = p.x; w = __int_as_float(p.y); }
        int cnt = min(32, e1 - base);
        #pragma unroll 4
        for (int j = 0; j < cnt; j++) {
            int   sj = __shfl_sync(0xffffffffu, s, j);
            float wj = __shfl_sync(0xffffffffu, w, j);
            uint32_t v[W2L];
            if constexpr (F == 128) {
                uint2 u = ((const uint2*)(h + (size_t)sj * F))[lane];
                v[0] = u.x; v[1] = u.y;
            } else {
                uint4 u = ((const uint4*)(h + (size_t)sj * F))[lane];
                v[0] = u.x; v[1] = u.y; v[2] = u.z; v[3] = u.w;
            }
            #pragma unroll
            for (int q = 0; q < W2L; q++) {
                float2 f = __half22float2(*(__half2*)&v[q]);
                acc[2*q]   += wj * f.x;
                acc[2*q+1] += wj * f.y;
            }
        }
    }
    uint32_t o[W2L];
    #pragma unroll
    for (int q = 0; q < W2L; q++) {
        __half2 hv = __floats2half2_rn(di * acc[2*q], di * acc[2*q+1]);
        o[q] = *(uint32_t*)&hv;
    }
    if constexpr (F == 128) {
        uint2 u; u.x = o[0]; u.y = o[1];
        ((uint2*)(oh + (size_t)node * F))[lane] = u;
    } else {
        uint4 u; u.x = o[0]; u.y = o[1]; u.z = o[2]; u.w = o[3];
        ((uint4*)(oh + (size_t)node * F))[lane] = u;
    }
}

// ---------------------------------------------------------------------------
// 5. pure-fp16 tensor-core GEMM: C = relu( A @ B^T + bias ), fp32 accumulate.
//    CTA 128x128, 256 thr. Stage covers k=64 (four k16 slabs), double buffer.
#define PITCH_B 32
#define TILE_B  4096
#define SLAB_B  8192             // one k16 slab: A, B tiles
#define STAGE_B (4 * SLAB_B)     // k=64 per stage

template <bool POOL>
__global__ void __launch_bounds__(256)
gemm_tc(const __half* __restrict__ A, const __half* __restrict__ B,
        const float* __restrict__ bias, __half* __restrict__ C,
        const int* __restrict__ batch, int M, int K) {
    extern __shared__ __align__(1024) char smem[];
    uint32_t sbase = smem_u32(smem);

    int tid = threadIdx.x;
    int wid = tid >> 5, lane = tid & 31;
    int wm = wid >> 2, wn = wid & 3;
    int m0 = blockIdx.y * 128, n0 = blockIdx.x * 128;

    float acc[4][4][4];
    #pragma unroll
    for (int i = 0; i < 4; i++)
        #pragma unroll
        for (int j = 0; j < 4; j++)
            #pragma unroll
            for (int q = 0; q < 4; q++) acc[i][j][q] = 0.0f;

    int nquad = K >> 6;            // k64 stages

    auto load_slab = [&](uint32_t sb, int k0) {
        #pragma unroll
        for (int i = 0; i < 2; i++) {
            int c = tid + i * 256;
            int tile = c >> 8, t = c & 255;
            int row = t >> 1, half = t & 1;
            uint32_t dst = sb + tile * TILE_B + row * PITCH_B +
                           ((half ^ ((row >> 2) & 1)) << 4);
            const __half* src;
            uint32_t sz = 16;
            if (tile == 0) {
                int gr = m0 + row;
                int cr = gr < M ? gr : (M - 1);
                src = A + (size_t)cr * K + k0 + half * 8;
                if (gr >= M) sz = 0;
            } else {
                src = B + (size_t)(n0 + row) * K + k0 + half * 8;
            }
            cp_async16(dst, src, sz);
        }
    };
    auto load_quad = [&](int stage, int p) {
        uint32_t sb = sbase + stage * STAGE_B;
        #pragma unroll
        for (int q = 0; q < 4; q++)
            load_slab(sb + q * SLAB_B, p * 64 + q * 16);
        CP_COMMIT();
    };

    int r = lane & 15, sel = lane >> 4;

    auto compute_slab = [&](uint32_t sb) {
        uint32_t sA = sb, sB = sb + TILE_B;
        uint32_t af[4][4];
        #pragma unroll
        for (int mi = 0; mi < 4; mi++) {
            int rowA = wm * 64 + mi * 16 + r;
            uint32_t off = rowA * PITCH_B + ((sel ^ ((rowA >> 2) & 1)) << 4);
            ldsm_x4(af[mi][0], af[mi][1], af[mi][2], af[mi][3], sA + off);
        }
        uint32_t bf[2][4];
        #pragma unroll
        for (int nj = 0; nj < 2; nj++) {
            int rowB = wn * 32 + nj * 16 + r;
            uint32_t off = rowB * PITCH_B + ((sel ^ ((rowB >> 2) & 1)) << 4);
            ldsm_x4(bf[nj][0], bf[nj][1], bf[nj][2], bf[nj][3], sB + off);
        }
        #pragma unroll
        for (int mi = 0; mi < 4; mi++) {
            #pragma unroll
            for (int nn = 0; nn < 4; nn++) {
                int nj = nn >> 1, hi8 = nn & 1;
                mma_fp16(acc[mi][nn], af[mi], bf[nj][hi8], bf[nj][hi8 + 2]);
            }
        }
    };

    load_quad(0, 0);

    for (int p = 0; p < nquad; p++) {
        if (p + 1 < nquad) load_quad((p + 1) & 1, p + 1);
        if (p + 1 < nquad) { CP_WAIT(1); } else { CP_WAIT(0); }
        __syncthreads();
        uint32_t sb = sbase + (p & 1) * STAGE_B;
        compute_slab(sb);
        compute_slab(sb + SLAB_B);
        compute_slab(sb + 2 * SLAB_B);
        compute_slab(sb + 3 * SLAB_B);
        __syncthreads();
    }

    // epilogue
    int qr = lane >> 2, qc = lane & 3;
    #pragma unroll
    for (int nn = 0; nn < 4; nn++) {
        int col = n0 + wn * 32 + (nn >> 1) * 16 + (nn & 1) * 8 + qc * 2;
        float bz0 = __ldg(&bias[col]), bz1 = __ldg(&bias[col + 1]);
        #pragma unroll
        for (int mi = 0; mi < 4; mi++) {
            int row0 = m0 + wm * 64 + mi * 16 + qr;
            if (row0 < M) {
                float v0 = fmaxf(acc[mi][nn][0] + bz0, 0.f);
                float v1 = fmaxf(acc[mi][nn][1] + bz1, 0.f);
                if (POOL) {
                    int g = __ldg(&batch[row0]);
                    atomicAdd(&g_sums[g * HID + col],     v0);
                    atomicAdd(&g_sums[g * HID + col + 1], v1);
                } else {
                    __half2 hv = __floats2half2_rn(v0, v1);
                    *(__half2*)(C + (size_t)row0 * 256 + col) = hv;
                }
            }
            int row1 = row0 + 8;
            if (row1 < M) {
                float v2 = fmaxf(acc[mi][nn][2] + bz0, 0.f);
                float v3 = fmaxf(acc[mi][nn][3] + bz1, 0.f);
                if (POOL) {
                    int g = __ldg(&batch[row1]);
                    atomicAdd(&g_sums[g * HID + col],     v2);
                    atomicAdd(&g_sums[g * HID + col + 1], v3);
                } else {
                    __half2 hv = __floats2half2_rn(v2, v3);
                    *(__half2*)(C + (size_t)row1 * 256 + col) = hv;
                }
            }
        }
    }
}

// ---------------------------------------------------------------------------
// 6. head: mean, concat, fc1(relu), fc2 -> out[G,16]
__global__ void head_kernel(const float* __restrict__ molwt, const float* __restrict__ nrings,
                            const float* __restrict__ fcW1, const float* __restrict__ fcb1,
                            const float* __restrict__ fcW2, const float* __restrict__ fcb2,
                            float* __restrict__ out) {
    int g = blockIdx.x;
    __shared__ float hg[258];
    __shared__ float h1[196];
    int t = threadIdx.x;  // 256
    float c = fmaxf((float)g_gcnt[g], 1.0f);
    hg[t] = g_sums[g * HID + t] / c;
    if (t == 0) { hg[256] = molwt[g]; hg[257] = nrings[g]; }
    __syncthreads();
    if (t < 196) {
        float a = fcb1[t];
        #pragma unroll 4
        for (int k = 0; k < 258; k++) a += hg[k] * fcW1[k * 196 + t];
        h1[t] = fmaxf(a, 0.0f);
    }
    __syncthreads();
    if (t < 16) {
        float a = fcb2[t];
        #pragma unroll 4
        for (int k = 0; k < 196; k++) a += h1[k] * fcW2[k * 16 + t];
        out[g * 16 + t] = a;
    }
}

// ---------------------------------------------------------------------------
extern "C" void kernel_launch(void* const* d_in, const int* in_sizes, int n_in,
                              void* d_out, int out_size) {
    const float* x      = (const float*)d_in[0];
    const int*   ei     = (const int*)  d_in[1];
    const int*   batch  = (const int*)  d_in[2];
    const float* molwt  = (const float*)d_in[3];
    const float* nrings = (const float*)d_in[4];
    const float* W1 = (const float*)d_in[5];
    const float* b1 = (const float*)d_in[6];
    const float* W2 = (const float*)d_in[7];
    const float* b2 = (const float*)d_in[8];
    const float* W3 = (const float*)d_in[9];
    const float* b3 = (const float*)d_in[10];
    const float* fcW1 = (const float*)d_in[11];
    const float* fcb1 = (const float*)d_in[12];
    const float* fcW2 = (const float*)d_in[13];
    const float* fcb2 = (const float*)d_in[14];

    const int N = in_sizes[2];
    const int E = in_sizes[1] / 2;
    const int G = in_sizes[3];
    const int F_IN = in_sizes[0] / N;   // 128

    __half *A, *H, *X16, *W1t, *W2t, *W3t;
    cudaGetSymbolAddress((void**)&A, g_A);
    cudaGetSymbolAddress((void**)&H, g_H);
    cudaGetSymbolAddress((void**)&X16, g_x16);
    cudaGetSymbolAddress((void**)&W1t, g_W1t);
    cudaGetSymbolAddress((void**)&W2t, g_W2t);
    cudaGetSymbolAddress((void**)&W3t, g_W3t);

    const int GEMM_SMEM = 2 * STAGE_B;   // 65536
    cudaFuncSetAttribute(gemm_tc<false>, cudaFuncAttributeMaxDynamicSharedMemorySize, GEMM_SMEM);
    cudaFuncSetAttribute(gemm_tc<true >, cudaFuncAttributeMaxDynamicSharedMemorySize, GEMM_SMEM);

    int nb = (N + 1023) / 1024;
    dim3 ggrid(2, (N + 127) / 128);
    int aggblocks = (N + 7) / 8;   // 8 warps / block

    // setup
    init_kernel<<<256, 256>>>(N, G);
    int stot = E + N + N * F_IN / 4 + F_IN * 256 + 2 * 256 * 256;
    setup_kernel<<<(stot + 255) / 256, 256>>>(ei, batch, x, X16, W1, W2, W3, E, N, F_IN);
    scan_p12<<<nb, 1024>>>(N, nb);
    scan_p3<<<nb, 1024>>>(N);
    fill_kernel<<<(E + 255) / 256, 256>>>(ei, E);

    // layer 1: fp16 x -> A, GEMM -> H
    agg_f16<128><<<aggblocks, 256>>>(X16, A, N);
    gemm_tc<false><<<ggrid, 256, GEMM_SMEM>>>(A, W1t, b1, H, nullptr, N, F_IN);
    // layer 2
    agg_f16<256><<<aggblocks, 256>>>(H, A, N);
    gemm_tc<false><<<ggrid, 256, GEMM_SMEM>>>(A, W2t, b2, H, nullptr, N, HID);
    // layer 3 (pooling fused into epilogue)
    agg_f16<256><<<aggblocks, 256>>>(H, A, N);
    gemm_tc<true><<<ggrid, 256, GEMM_SMEM>>>(A, W3t, b3, nullptr, batch, N, HID);

    // head
    head_kernel<<<G, 256>>>(molwt, nrings, fcW1, fcb1, fcW2, fcb2, (float*)d_out);
}

// round 16
// speedup vs baseline: 1.2358x; 1.0058x over previous
#include <cuda_runtime.h>
#include <cuda_fp16.h>
#include <cstdint>
#include <math.h>

// Problem constants (fixed for this dataset)
#define MAXN 50000
#define MAXE 800000
#define MAXG 512
#define HID  256

// ---------------------------------------------------------------------------
// Scratch (__device__ globals). Arrays needing zero at call entry are zeroed
// by their LAST READER each call (statics start zero on the first call):
//   g_counts -> zeroed in scan_p3, g_gcnt/g_sums -> zeroed in head_kernel,
//   g_tick   -> self-resets in scan_p12.
__device__ __half g_A[(size_t)MAXN * HID];            // agg output, fp16
__device__ __half g_H[(size_t)MAXN * HID];            // hidden state, fp16
__device__ __half g_x16[(size_t)MAXN * 128];          // fp16 copy of input x
__device__ float g_dis[MAXN];
__device__ int   g_counts[MAXN];
__device__ int   g_offs[MAXN + 1];
__device__ int   g_wptr[MAXN];
__device__ int2  g_csr2[MAXE];                        // {src, bits(dis[src])}
__device__ float g_sums[MAXG * HID];
__device__ int   g_gcnt[MAXG];
__device__ int   g_bsum[64];
__device__ int   g_tick;
// transposed weights: [N=256 rows][K cols], K-major fp16
__device__ __half g_W1t[256 * 128];
__device__ __half g_W2t[256 * 256];
__device__ __half g_W3t[256 * 256];

// ---------------------------------------------------------------------------
// base-ISA tensor helpers (mma.sync / ldmatrix / cp.async)
__device__ __forceinline__ void ldsm_x4(uint32_t& r0, uint32_t& r1, uint32_t& r2, uint32_t& r3,
                                        uint32_t addr) {
    asm volatile("ldmatrix.sync.aligned.m8n8.x4.shared.b16 {%0,%1,%2,%3}, [%4];"
                 : "=r"(r0), "=r"(r1), "=r"(r2), "=r"(r3) : "r"(addr));
}
__device__ __forceinline__ void mma_fp16(float* c, const uint32_t* a, uint32_t b0, uint32_t b1) {
    asm volatile("mma.sync.aligned.m16n8k16.row.col.f32.f16.f16.f32 "
                 "{%0,%1,%2,%3}, {%4,%5,%6,%7}, {%8,%9}, {%0,%1,%2,%3};"
                 : "+f"(c[0]), "+f"(c[1]), "+f"(c[2]), "+f"(c[3])
                 : "r"(a[0]), "r"(a[1]), "r"(a[2]), "r"(a[3]), "r"(b0), "r"(b1));
}
__device__ __forceinline__ void cp_async16(uint32_t smem_addr, const void* gptr, uint32_t src_sz) {
    asm volatile("cp.async.cg.shared.global [%0], [%1], 16, %2;"
                 :: "r"(smem_addr), "l"(gptr), "r"(src_sz) : "memory");
}
#define CP_COMMIT() asm volatile("cp.async.commit_group;" ::: "memory")
#define CP_WAIT(n)  asm volatile("cp.async.wait_group %0;" :: "n"(n) : "memory")
__device__ __forceinline__ uint32_t smem_u32(const void* p) {
    uint32_t a;
    asm("{ .reg .u64 t; cvta.to.shared.u64 t, %1; cvt.u32.u64 %0, t; }" : "=r"(a) : "l"(p));
    return a;
}

// ---------------------------------------------------------------------------
// 0. merged setup: degree counts + graph counts + x->fp16 + weight transposes
__global__ void setup_kernel(const int* __restrict__ ei, const int* __restrict__ batch,
                             const float* __restrict__ x, __half* __restrict__ x16,
                             const float* __restrict__ W1, const float* __restrict__ W2,
                             const float* __restrict__ W3,
                             int E, int N, int K1) {
    int i = blockIdx.x * blockDim.x + threadIdx.x;
    if (i < E) { atomicAdd(&g_counts[ei[E + i]], 1); return; }
    i -= E;
    if (i < N) { atomicAdd(&g_gcnt[batch[i]], 1); return; }
    i -= N;
    int x4 = N * K1 / 4;
    if (i < x4) {
        float4 f = ((const float4*)x)[i];
        __half2 a = __floats2half2_rn(f.x, f.y);
        __half2 b = __floats2half2_rn(f.z, f.w);
        uint2 u; u.x = *(uint32_t*)&a; u.y = *(uint32_t*)&b;
        ((uint2*)x16)[i] = u;
        return;
    }
    i -= x4;
    int sz1 = K1 * 256, sz23 = 256 * 256;
    const float* W; __half* Wt; int idx, K;
    if (i < sz1)               { W = W1; Wt = g_W1t; idx = i;              K = K1;  }
    else if (i < sz1 + sz23)   { W = W2; Wt = g_W2t; idx = i - sz1;        K = 256; }
    else if (i < sz1 + 2*sz23) { W = W3; Wt = g_W3t; idx = i - sz1 - sz23; K = 256; }
    else return;
    int k = idx / 256, n = idx % 256;
    Wt[n * K + k] = __float2half_rn(W[idx]);
}
// 1. fused per-block reduce + (last block) scan of block sums; ticket self-resets
__global__ void scan_p12(int n, int nb) {
    int i = blockIdx.x * 1024 + threadIdx.x;
    int v = (i < n) ? g_counts[i] : 0;
    __shared__ int sw[32];
    __shared__ int isLast;
    int lane = threadIdx.x & 31, wid = threadIdx.x >> 5;
    int s = v;
    #pragma unroll
    for (int o = 16; o > 0; o >>= 1) s += __shfl_down_sync(0xffffffffu, s, o);
    if (lane == 0) sw[wid] = s;
    __syncthreads();
    if (wid == 0) {
        int t = sw[lane];
        #pragma unroll
        for (int o = 16; o > 0; o >>= 1) t += __shfl_down_sync(0xffffffffu, t, o);
        if (lane == 0) g_bsum[blockIdx.x] = t;
    }
    if (threadIdx.x == 0) {
        __threadfence();
        isLast = (atomicAdd(&g_tick, 1) == nb - 1);
    }
    __syncthreads();
    if (isLast && wid == 1) {
        if (lane == 0) {
            g_tick = 0;  // reset for next call
            int run = 0;
            for (int b = 0; b < nb; b++) {
                int t = g_bsum[b];
                g_bsum[b] = run;
                run += t;
            }
            g_offs[n] = run;
            __threadfence();
        }
    }
}
// 2. per-block inclusive scan + base -> offs/wptr/dis; zeros counts (last reader)
__global__ void scan_p3(int n) {
    int base = g_bsum[blockIdx.x];
    int i = blockIdx.x * 1024 + threadIdx.x;
    int v = (i < n) ? g_counts[i] : 0;
    __shared__ int sw[32];
    int lane = threadIdx.x & 31, wid = threadIdx.x >> 5;
    int inc = v;
    #pragma unroll
    for (int o = 1; o < 32; o <<= 1) {
        int t = __shfl_up_sync(0xffffffffu, inc, o);
        if (lane >= o) inc += t;
    }
    if (lane == 31) sw[wid] = inc;
    __syncthreads();
    if (wid == 0) {
        int t = sw[lane];
        #pragma unroll
        for (int o = 1; o < 32; o <<= 1) {
            int u = __shfl_up_sync(0xffffffffu, t, o);
            if (lane >= o) t += u;
        }
        sw[lane] = t;
    }
    __syncthreads();
    int excl = base + inc - v + (wid > 0 ? sw[wid - 1] : 0);
    if (i < n) {
        g_offs[i] = excl;
        g_wptr[i] = excl;
        g_dis[i]  = rsqrtf(1.0f + (float)v);
        g_counts[i] = 0;                       // reset for next call
    }
}
// 3. fill CSR with packed {src, dis[src]}; two edges per thread for MLP
__global__ void fill_kernel(const int* __restrict__ ei, int E) {
    int e = blockIdx.x * blockDim.x + threadIdx.x;
    int E2 = (E + 1) >> 1;
    if (e < E2) {
        int s0 = ei[e], d0 = ei[E + e];
        int e1 = e + E2;
        int s1 = 0, d1 = 0;
        bool has1 = (e1 < E);
        if (has1) { s1 = ei[e1]; d1 = ei[E + e1]; }
        float w0 = g_dis[s0];
        float w1 = has1 ? g_dis[s1] : 0.0f;
        int p0 = atomicAdd(&g_wptr[d0], 1);
        g_csr2[p0] = make_int2(s0, __float_as_int(w0));
        if (has1) {
            int p1 = atomicAdd(&g_wptr[d1], 1);
            g_csr2[p1] = make_int2(s1, __float_as_int(w1));
        }
    }
}

// ---------------------------------------------------------------------------
// 4. warp-per-node aggregation on fp16 rows -> fp16 out. F in {128, 256}.
template <int F>
__global__ void agg_f16(const __half* __restrict__ h, __half* __restrict__ oh, int N) {
    constexpr int HPL = F / 32;
    constexpr int W2L = HPL / 2;
    int node = blockIdx.x * (blockDim.x >> 5) + (threadIdx.x >> 5);
    int lane = threadIdx.x & 31;
    if (node >= N) return;

    float di = g_dis[node];
    float acc[HPL];
    {
        uint32_t v[W2L];
        if constexpr (F == 128) {
            uint2 u = ((const uint2*)(h + (size_t)node * F))[lane];
            v[0] = u.x; v[1] = u.y;
        } else {
            uint4 u = ((const uint4*)(h + (size_t)node * F))[lane];
            v[0] = u.x; v[1] = u.y; v[2] = u.z; v[3] = u.w;
        }
        #pragma unroll
        for (int q = 0; q < W2L; q++) {
            float2 f = __half22float2(*(__half2*)&v[q]);
            acc[2*q]   = di * f.x;
            acc[2*q+1] = di * f.y;
        }
    }
    int e0 = g_offs[node], e1 = g_offs[node + 1];
    for (int base = e0; base < e1; base += 32) {
        int e = base + lane;
        int s = 0; float w = 0.0f;
        if (e < e1) { int2 p = g_csr2[e]; s = p.x; w = __int_as_float(p.y); }
        int cnt = min(32, e1 - base);
        #pragma unroll 4
        for (int j = 0; j < cnt; j++) {
            int   sj = __shfl_sync(0xffffffffu, s, j);
            float wj = __shfl_sync(0xffffffffu, w, j);
            uint32_t v[W2L];
            if constexpr (F == 128) {
                uint2 u = ((const uint2*)(h + (size_t)sj * F))[lane];
                v[0] = u.x; v[1] = u.y;
            } else {
                uint4 u = ((const uint4*)(h + (size_t)sj * F))[lane];
                v[0] = u.x; v[1] = u.y; v[2] = u.z; v[3] = u.w;
            }
            #pragma unroll
            for (int q = 0; q < W2L; q++) {
                float2 f = __half22float2(*(__half2*)&v[q]);
                acc[2*q]   += wj * f.x;
                acc[2*q+1] += wj * f.y;
            }
        }
    }
    uint32_t o[W2L];
    #pragma unroll
    for (int q = 0; q < W2L; q++) {
        __half2 hv = __floats2half2_rn(di * acc[2*q], di * acc[2*q+1]);
        o[q] = *(uint32_t*)&hv;
    }
    if constexpr (F == 128) {
        uint2 u; u.x = o[0]; u.y = o[1];
        ((uint2*)(oh + (size_t)node * F))[lane] = u;
    } else {
        uint4 u; u.x = o[0]; u.y = o[1]; u.z = o[2]; u.w = o[3];
        ((uint4*)(oh + (size_t)node * F))[lane] = u;
    }
}

// ---------------------------------------------------------------------------
// 5. pure-fp16 tensor-core GEMM: C = relu( A @ B^T + bias ), fp32 accumulate.
//    CTA 128x128, 256 thr. Stage covers k=64 (four k16 slabs), double buffer.
#define PITCH_B 32
#define TILE_B  4096
#define SLAB_B  8192             // one k16 slab: A, B tiles
#define STAGE_B (4 * SLAB_B)     // k=64 per stage

template <bool POOL>
__global__ void __launch_bounds__(256)
gemm_tc(const __half* __restrict__ A, const __half* __restrict__ B,
        const float* __restrict__ bias, __half* __restrict__ C,
        const int* __restrict__ batch, int M, int K) {
    extern __shared__ __align__(1024) char smem[];
    uint32_t sbase = smem_u32(smem);

    int tid = threadIdx.x;
    int wid = tid >> 5, lane = tid & 31;
    int wm = wid >> 2, wn = wid & 3;
    int m0 = blockIdx.y * 128, n0 = blockIdx.x * 128;

    float acc[4][4][4];
    #pragma unroll
    for (int i = 0; i < 4; i++)
        #pragma unroll
        for (int j = 0; j < 4; j++)
            #pragma unroll
            for (int q = 0; q < 4; q++) acc[i][j][q] = 0.0f;

    int nquad = K >> 6;

    auto load_slab = [&](uint32_t sb, int k0) {
        #pragma unroll
        for (int i = 0; i < 2; i++) {
            int c = tid + i * 256;
            int tile = c >> 8, t = c & 255;
            int row = t >> 1, half = t & 1;
            uint32_t dst = sb + tile * TILE_B + row * PITCH_B +
                           ((half ^ ((row >> 2) & 1)) << 4);
            const __half* src;
            uint32_t sz = 16;
            if (tile == 0) {
                int gr = m0 + row;
                int cr = gr < M ? gr : (M - 1);
                src = A + (size_t)cr * K + k0 + half * 8;
                if (gr >= M) sz = 0;
            } else {
                src = B + (size_t)(n0 + row) * K + k0 + half * 8;
            }
            cp_async16(dst, src, sz);
        }
    };
    auto load_quad = [&](int stage, int p) {
        uint32_t sb = sbase + stage * STAGE_B;
        #pragma unroll
        for (int q = 0; q < 4; q++)
            load_slab(sb + q * SLAB_B, p * 64 + q * 16);
        CP_COMMIT();
    };

    int r = lane & 15, sel = lane >> 4;

    auto compute_slab = [&](uint32_t sb) {
        uint32_t sA = sb, sB = sb + TILE_B;
        uint32_t af[4][4];
        #pragma unroll
        for (int mi = 0; mi < 4; mi++) {
            int rowA = wm * 64 + mi * 16 + r;
            uint32_t off = rowA * PITCH_B + ((sel ^ ((rowA >> 2) & 1)) << 4);
            ldsm_x4(af[mi][0], af[mi][1], af[mi][2], af[mi][3], sA + off);
        }
        uint32_t bf[2][4];
        #pragma unroll
        for (int nj = 0; nj < 2; nj++) {
            int rowB = wn * 32 + nj * 16 + r;
            uint32_t off = rowB * PITCH_B + ((sel ^ ((rowB >> 2) & 1)) << 4);
            ldsm_x4(bf[nj][0], bf[nj][1], bf[nj][2], bf[nj][3], sB + off);
        }
        #pragma unroll
        for (int mi = 0; mi < 4; mi++) {
            #pragma unroll
            for (int nn = 0; nn < 4; nn++) {
                int nj = nn >> 1, hi8 = nn & 1;
                mma_fp16(acc[mi][nn], af[mi], bf[nj][hi8], bf[nj][hi8 + 2]);
            }
        }
    };

    load_quad(0, 0);

    for (int p = 0; p < nquad; p++) {
        if (p + 1 < nquad) load_quad((p + 1) & 1, p + 1);
        if (p + 1 < nquad) { CP_WAIT(1); } else { CP_WAIT(0); }
        __syncthreads();
        uint32_t sb = sbase + (p & 1) * STAGE_B;
        compute_slab(sb);
        compute_slab(sb + SLAB_B);
        compute_slab(sb + 2 * SLAB_B);
        compute_slab(sb + 3 * SLAB_B);
        __syncthreads();
    }

    // epilogue
    int qr = lane >> 2, qc = lane & 3;
    #pragma unroll
    for (int nn = 0; nn < 4; nn++) {
        int col = n0 + wn * 32 + (nn >> 1) * 16 + (nn & 1) * 8 + qc * 2;
        float bz0 = __ldg(&bias[col]), bz1 = __ldg(&bias[col + 1]);
        #pragma unroll
        for (int mi = 0; mi < 4; mi++) {
            int row0 = m0 + wm * 64 + mi * 16 + qr;
            if (row0 < M) {
                float v0 = fmaxf(acc[mi][nn][0] + bz0, 0.f);
                float v1 = fmaxf(acc[mi][nn][1] + bz1, 0.f);
                if (POOL) {
                    int g = __ldg(&batch[row0]);
                    atomicAdd(&g_sums[g * HID + col],     v0);
                    atomicAdd(&g_sums[g * HID + col + 1], v1);
                } else {
                    __half2 hv = __floats2half2_rn(v0, v1);
                    *(__half2*)(C + (size_t)row0 * 256 + col) = hv;
                }
            }
            int row1 = row0 + 8;
            if (row1 < M) {
                float v2 = fmaxf(acc[mi][nn][2] + bz0, 0.f);
                float v3 = fmaxf(acc[mi][nn][3] + bz1, 0.f);
                if (POOL) {
                    int g = __ldg(&batch[row1]);
                    atomicAdd(&g_sums[g * HID + col],     v2);
                    atomicAdd(&g_sums[g * HID + col + 1], v3);
                } else {
                    __half2 hv = __floats2half2_rn(v2, v3);
                    *(__half2*)(C + (size_t)row1 * 256 + col) = hv;
                }
            }
        }
    }
}

// ---------------------------------------------------------------------------
// 6. head: mean, concat, fc1(relu), fc2 -> out[G,16].
//    Also zeroes g_sums / g_gcnt after reading (last reader; next-call reset).
__global__ void head_kernel(const float* __restrict__ molwt, const float* __restrict__ nrings,
                            const float* __restrict__ fcW1, const float* __restrict__ fcb1,
                            const float* __restrict__ fcW2, const float* __restrict__ fcb2,
                            float* __restrict__ out) {
    int g = blockIdx.x;
    __shared__ float hg[258];
    __shared__ float h1[196];
    int t = threadIdx.x;  // 256
    float c = fmaxf((float)g_gcnt[g], 1.0f);
    hg[t] = g_sums[g * HID + t] / c;
    g_sums[g * HID + t] = 0.0f;          // reset for next call
    if (t == 0) {
        hg[256] = molwt[g]; hg[257] = nrings[g];
        g_gcnt[g] = 0;                   // reset for next call
    }
    __syncthreads();
    if (t < 196) {
        float a = fcb1[t];
        #pragma unroll 4
        for (int k = 0; k < 258; k++) a += hg[k] * fcW1[k * 196 + t];
        h1[t] = fmaxf(a, 0.0f);
    }
    __syncthreads();
    if (t < 16) {
        float a = fcb2[t];
        #pragma unroll 4
        for (int k = 0; k < 196; k++) a += h1[k] * fcW2[k * 16 + t];
        out[g * 16 + t] = a;
    }
}

// ---------------------------------------------------------------------------
extern "C" void kernel_launch(void* const* d_in, const int* in_sizes, int n_in,
                              void* d_out, int out_size) {
    const float* x      = (const float*)d_in[0];
    const int*   ei     = (const int*)  d_in[1];
    const int*   batch  = (const int*)  d_in[2];
    const float* molwt  = (const float*)d_in[3];
    const float* nrings = (const float*)d_in[4];
    const float* W1 = (const float*)d_in[5];
    const float* b1 = (const float*)d_in[6];
    const float* W2 = (const float*)d_in[7];
    const float* b2 = (const float*)d_in[8];
    const float* W3 = (const float*)d_in[9];
    const float* b3 = (const float*)d_in[10];
    const float* fcW1 = (const float*)d_in[11];
    const float* fcb1 = (const float*)d_in[12];
    const float* fcW2 = (const float*)d_in[13];
    const float* fcb2 = (const float*)d_in[14];

    const int N = in_sizes[2];
    const int E = in_sizes[1] / 2;
    const int G = in_sizes[3];
    const int F_IN = in_sizes[0] / N;   // 128

    __half *A, *H, *X16, *W1t, *W2t, *W3t;
    cudaGetSymbolAddress((void**)&A, g_A);
    cudaGetSymbolAddress((void**)&H, g_H);
    cudaGetSymbolAddress((void**)&X16, g_x16);
    cudaGetSymbolAddress((void**)&W1t, g_W1t);
    cudaGetSymbolAddress((void**)&W2t, g_W2t);
    cudaGetSymbolAddress((void**)&W3t, g_W3t);

    const int GEMM_SMEM = 2 * STAGE_B;   // 65536
    cudaFuncSetAttribute(gemm_tc<false>, cudaFuncAttributeMaxDynamicSharedMemorySize, GEMM_SMEM);
    cudaFuncSetAttribute(gemm_tc<true >, cudaFuncAttributeMaxDynamicSharedMemorySize, GEMM_SMEM);

    int nb = (N + 1023) / 1024;
    dim3 ggrid(2, (N + 127) / 128);
    int aggblocks = (N + 7) / 8;   // 8 warps / block

    // setup (no init kernel: scratch is reset by last readers each call)
    int stot = E + N + N * F_IN / 4 + F_IN * 256 + 2 * 256 * 256;
    setup_kernel<<<(stot + 255) / 256, 256>>>(ei, batch, x, X16, W1, W2, W3, E, N, F_IN);
    scan_p12<<<nb, 1024>>>(N, nb);
    scan_p3<<<nb, 1024>>>(N);
    int E2 = (E + 1) / 2;
    fill_kernel<<<(E2 + 255) / 256, 256>>>(ei, E);

    // layer 1: fp16 x -> A, GEMM -> H
    agg_f16<128><<<aggblocks, 256>>>(X16, A, N);
    gemm_tc<false><<<ggrid, 256, GEMM_SMEM>>>(A, W1t, b1, H, nullptr, N, F_IN);
    // layer 2
    agg_f16<256><<<aggblocks, 256>>>(H, A, N);
    gemm_tc<false><<<ggrid, 256, GEMM_SMEM>>>(A, W2t, b2, H, nullptr, N, HID);
    // layer 3 (pooling fused into epilogue)
    agg_f16<256><<<aggblocks, 256>>>(H, A, N);
    gemm_tc<true><<<ggrid, 256, GEMM_SMEM>>>(A, W3t, b3, nullptr, batch, N, HID);

    // head (also resets g_sums / g_gcnt for the next replay)
    head_kernel<<<G, 256>>>(molwt, nrings, fcW1, fcb1, fcW2, fcb2, (float*)d_out);
}

// round 17
// speedup vs baseline: 1.2924x; 1.0458x over previous
#include <cuda_runtime.h>
#include <cuda_fp16.h>
#include <cstdint>
#include <math.h>

// Problem constants (fixed for this dataset)
#define MAXN 50000
#define MAXE 800000
#define MAXG 512
#define HID  256

// ---------------------------------------------------------------------------
// Scratch (__device__ globals). Zero-at-entry arrays are reset by their LAST
// READER each call (statics start zero on the first call):
//   g_counts -> zeroed in scan_p3, g_tick -> self-resets in scan_p12.
__device__ __half g_A[(size_t)MAXN * HID];            // agg output, fp16
__device__ __half g_H[(size_t)MAXN * HID];            // hidden state, fp16
__device__ __half g_x16[(size_t)MAXN * 128];          // fp16 copy of input x
__device__ float g_dis[MAXN];
__device__ int   g_counts[MAXN];
__device__ int   g_offs[MAXN + 1];
__device__ int   g_wptr[MAXN];
__device__ int2  g_csr2[MAXE];                        // {src, bits(dis[src])}
__device__ int   g_gstart[MAXG + 1];                  // per-graph row ranges (sorted batch)
__device__ int   g_bsum[64];
__device__ int   g_tick;
// transposed weights: [N=256 rows][K cols], K-major fp16
__device__ __half g_W1t[256 * 128];
__device__ __half g_W2t[256 * 256];
__device__ __half g_W3t[256 * 256];

// ---------------------------------------------------------------------------
// base-ISA tensor helpers (mma.sync / ldmatrix / cp.async)
__device__ __forceinline__ void ldsm_x4(uint32_t& r0, uint32_t& r1, uint32_t& r2, uint32_t& r3,
                                        uint32_t addr) {
    asm volatile("ldmatrix.sync.aligned.m8n8.x4.shared.b16 {%0,%1,%2,%3}, [%4];"
                 : "=r"(r0), "=r"(r1), "=r"(r2), "=r"(r3) : "r"(addr));
}
__device__ __forceinline__ void mma_fp16(float* c, const uint32_t* a, uint32_t b0, uint32_t b1) {
    asm volatile("mma.sync.aligned.m16n8k16.row.col.f32.f16.f16.f32 "
                 "{%0,%1,%2,%3}, {%4,%5,%6,%7}, {%8,%9}, {%0,%1,%2,%3};"
                 : "+f"(c[0]), "+f"(c[1]), "+f"(c[2]), "+f"(c[3])
                 : "r"(a[0]), "r"(a[1]), "r"(a[2]), "r"(a[3]), "r"(b0), "r"(b1));
}
__device__ __forceinline__ void cp_async16(uint32_t smem_addr, const void* gptr, uint32_t src_sz) {
    asm volatile("cp.async.cg.shared.global [%0], [%1], 16, %2;"
                 :: "r"(smem_addr), "l"(gptr), "r"(src_sz) : "memory");
}
#define CP_COMMIT() asm volatile("cp.async.commit_group;" ::: "memory")
#define CP_WAIT(n)  asm volatile("cp.async.wait_group %0;" :: "n"(n) : "memory")
__device__ __forceinline__ uint32_t smem_u32(const void* p) {
    uint32_t a;
    asm("{ .reg .u64 t; cvta.to.shared.u64 t, %1; cvt.u32.u64 %0, t; }" : "=r"(a) : "l"(p));
    return a;
}

// ---------------------------------------------------------------------------
// 0. merged setup: degree counts + gstart boundaries + x->fp16 + weight transposes
__global__ void setup_kernel(const int* __restrict__ ei, const int* __restrict__ batch,
                             const float* __restrict__ x, __half* __restrict__ x16,
                             const float* __restrict__ W1, const float* __restrict__ W2,
                             const float* __restrict__ W3,
                             int E, int N, int K1, int G) {
    int i = blockIdx.x * blockDim.x + threadIdx.x;
    if (i < E) { atomicAdd(&g_counts[ei[E + i]], 1); return; }
    i -= E;
    if (i < N) {
        // gstart from sorted batch: boundary writes, no atomics
        int b = batch[i];
        if (i == 0) {
            for (int g = 0; g <= b; g++) g_gstart[g] = 0;
        } else {
            int pb = batch[i - 1];
            for (int g = pb + 1; g <= b; g++) g_gstart[g] = i;
        }
        if (i == N - 1) {
            for (int g = b + 1; g <= G; g++) g_gstart[g] = N;
        }
        return;
    }
    i -= N;
    int x4 = N * K1 / 4;
    if (i < x4) {
        float4 f = ((const float4*)x)[i];
        __half2 a = __floats2half2_rn(f.x, f.y);
        __half2 b = __floats2half2_rn(f.z, f.w);
        uint2 u; u.x = *(uint32_t*)&a; u.y = *(uint32_t*)&b;
        ((uint2*)x16)[i] = u;
        return;
    }
    i -= x4;
    int sz1 = K1 * 256, sz23 = 256 * 256;
    const float* W; __half* Wt; int idx, K;
    if (i < sz1)               { W = W1; Wt = g_W1t; idx = i;              K = K1;  }
    else if (i < sz1 + sz23)   { W = W2; Wt = g_W2t; idx = i - sz1;        K = 256; }
    else if (i < sz1 + 2*sz23) { W = W3; Wt = g_W3t; idx = i - sz1 - sz23; K = 256; }
    else return;
    int k = idx / 256, n = idx % 256;
    Wt[n * K + k] = __float2half_rn(W[idx]);
}
// 1. fused per-block reduce + (last block) scan of block sums; ticket self-resets
__global__ void scan_p12(int n, int nb) {
    int i = blockIdx.x * 1024 + threadIdx.x;
    int v = (i < n) ? g_counts[i] : 0;
    __shared__ int sw[32];
    __shared__ int isLast;
    int lane = threadIdx.x & 31, wid = threadIdx.x >> 5;
    int s = v;
    #pragma unroll
    for (int o = 16; o > 0; o >>= 1) s += __shfl_down_sync(0xffffffffu, s, o);
    if (lane == 0) sw[wid] = s;
    __syncthreads();
    if (wid == 0) {
        int t = sw[lane];
        #pragma unroll
        for (int o = 16; o > 0; o >>= 1) t += __shfl_down_sync(0xffffffffu, t, o);
        if (lane == 0) g_bsum[blockIdx.x] = t;
    }
    if (threadIdx.x == 0) {
        __threadfence();
        isLast = (atomicAdd(&g_tick, 1) == nb - 1);
    }
    __syncthreads();
    if (isLast && wid == 1) {
        if (lane == 0) {
            g_tick = 0;  // reset for next call
            int run = 0;
            for (int b = 0; b < nb; b++) {
                int t = g_bsum[b];
                g_bsum[b] = run;
                run += t;
            }
            g_offs[n] = run;
            __threadfence();
        }
    }
}
// 2. per-block inclusive scan + base -> offs/wptr/dis; zeros counts (last reader)
__global__ void scan_p3(int n) {
    int base = g_bsum[blockIdx.x];
    int i = blockIdx.x * 1024 + threadIdx.x;
    int v = (i < n) ? g_counts[i] : 0;
    __shared__ int sw[32];
    int lane = threadIdx.x & 31, wid = threadIdx.x >> 5;
    int inc = v;
    #pragma unroll
    for (int o = 1; o < 32; o <<= 1) {
        int t = __shfl_up_sync(0xffffffffu, inc, o);
        if (lane >= o) inc += t;
    }
    if (lane == 31) sw[wid] = inc;
    __syncthreads();
    if (wid == 0) {
        int t = sw[lane];
        #pragma unroll
        for (int o = 1; o < 32; o <<= 1) {
            int u = __shfl_up_sync(0xffffffffu, t, o);
            if (lane >= o) t += u;
        }
        sw[lane] = t;
    }
    __syncthreads();
    int excl = base + inc - v + (wid > 0 ? sw[wid - 1] : 0);
    if (i < n) {
        g_offs[i] = excl;
        g_wptr[i] = excl;
        g_dis[i]  = rsqrtf(1.0f + (float)v);
        g_counts[i] = 0;                       // reset for next call
    }
}
// 3. fill CSR with packed {src, dis[src]}; two edges per thread for MLP
__global__ void fill_kernel(const int* __restrict__ ei, int E) {
    int e = blockIdx.x * blockDim.x + threadIdx.x;
    int E2 = (E + 1) >> 1;
    if (e < E2) {
        int s0 = ei[e], d0 = ei[E + e];
        int e1 = e + E2;
        int s1 = 0, d1 = 0;
        bool has1 = (e1 < E);
        if (has1) { s1 = ei[e1]; d1 = ei[E + e1]; }
        float w0 = g_dis[s0];
        float w1 = has1 ? g_dis[s1] : 0.0f;
        int p0 = atomicAdd(&g_wptr[d0], 1);
        g_csr2[p0] = make_int2(s0, __float_as_int(w0));
        if (has1) {
            int p1 = atomicAdd(&g_wptr[d1], 1);
            g_csr2[p1] = make_int2(s1, __float_as_int(w1));
        }
    }
}

// ---------------------------------------------------------------------------
// 4. warp-per-node aggregation on fp16 rows -> fp16 out. F in {128, 256}.
template <int F>
__global__ void agg_f16(const __half* __restrict__ h, __half* __restrict__ oh, int N) {
    constexpr int HPL = F / 32;
    constexpr int W2L = HPL / 2;
    int node = blockIdx.x * (blockDim.x >> 5) + (threadIdx.x >> 5);
    int lane = threadIdx.x & 31;
    if (node >= N) return;

    float di = g_dis[node];
    float acc[HPL];
    {
        uint32_t v[W2L];
        if constexpr (F == 128) {
            uint2 u = ((const uint2*)(h + (size_t)node * F))[lane];
            v[0] = u.x; v[1] = u.y;
        } else {
            uint4 u = ((const uint4*)(h + (size_t)node * F))[lane];
            v[0] = u.x; v[1] = u.y; v[2] = u.z; v[3] = u.w;
        }
        #pragma unroll
        for (int q = 0; q < W2L; q++) {
            float2 f = __half22float2(*(__half2*)&v[q]);
            acc[2*q]   = di * f.x;
            acc[2*q+1] = di * f.y;
        }
    }
    int e0 = g_offs[node], e1 = g_offs[node + 1];
    for (int base = e0; base < e1; base += 32) {
        int e = base + lane;
        int s = 0; float w = 0.0f;
        if (e < e1) { int2 p = g_csr2[e]; s = p.x; w = __int_as_float(p.y); }
        int cnt = min(32, e1 - base);
        #pragma unroll 4
        for (int j = 0; j < cnt; j++) {
            int   sj = __shfl_sync(0xffffffffu, s, j);
            float wj = __shfl_sync(0xffffffffu, w, j);
            uint32_t v[W2L];
            if constexpr (F == 128) {
                uint2 u = ((const uint2*)(h + (size_t)sj * F))[lane];
                v[0] = u.x; v[1] = u.y;
            } else {
                uint4 u = ((const uint4*)(h + (size_t)sj * F))[lane];
                v[0] = u.x; v[1] = u.y; v[2] = u.z; v[3] = u.w;
            }
            #pragma unroll
            for (int q = 0; q < W2L; q++) {
                float2 f = __half22float2(*(__half2*)&v[q]);
                acc[2*q]   += wj * f.x;
                acc[2*q+1] += wj * f.y;
            }
        }
    }
    uint32_t o[W2L];
    #pragma unroll
    for (int q = 0; q < W2L; q++) {
        __half2 hv = __floats2half2_rn(di * acc[2*q], di * acc[2*q+1]);
        o[q] = *(uint32_t*)&hv;
    }
    if constexpr (F == 128) {
        uint2 u; u.x = o[0]; u.y = o[1];
        ((uint2*)(oh + (size_t)node * F))[lane] = u;
    } else {
        uint4 u; u.x = o[0]; u.y = o[1]; u.z = o[2]; u.w = o[3];
        ((uint4*)(oh + (size_t)node * F))[lane] = u;
    }
}

// ---------------------------------------------------------------------------
// 5. pure-fp16 tensor-core GEMM: C = relu( A @ B^T + bias ), fp32 accumulate.
//    CTA 128x128, 256 thr. Stage covers k=64 (four k16 slabs), double buffer.
#define PITCH_B 32
#define TILE_B  4096
#define SLAB_B  8192             // one k16 slab: A, B tiles
#define STAGE_B (4 * SLAB_B)     // k=64 per stage

__global__ void __launch_bounds__(256)
gemm_tc(const __half* __restrict__ A, const __half* __restrict__ B,
        const float* __restrict__ bias, __half* __restrict__ C, int M, int K) {
    extern __shared__ __align__(1024) char smem[];
    uint32_t sbase = smem_u32(smem);

    int tid = threadIdx.x;
    int wid = tid >> 5, lane = tid & 31;
    int wm = wid >> 2, wn = wid & 3;
    int m0 = blockIdx.y * 128, n0 = blockIdx.x * 128;

    float acc[4][4][4];
    #pragma unroll
    for (int i = 0; i < 4; i++)
        #pragma unroll
        for (int j = 0; j < 4; j++)
            #pragma unroll
            for (int q = 0; q < 4; q++) acc[i][j][q] = 0.0f;

    int nquad = K >> 6;

    auto load_slab = [&](uint32_t sb, int k0) {
        #pragma unroll
        for (int i = 0; i < 2; i++) {
            int c = tid + i * 256;
            int tile = c >> 8, t = c & 255;
            int row = t >> 1, half = t & 1;
            uint32_t dst = sb + tile * TILE_B + row * PITCH_B +
                           ((half ^ ((row >> 2) & 1)) << 4);
            const __half* src;
            uint32_t sz = 16;
            if (tile == 0) {
                int gr = m0 + row;
                int cr = gr < M ? gr : (M - 1);
                src = A + (size_t)cr * K + k0 + half * 8;
                if (gr >= M) sz = 0;
            } else {
                src = B + (size_t)(n0 + row) * K + k0 + half * 8;
            }
            cp_async16(dst, src, sz);
        }
    };
    auto load_quad = [&](int stage, int p) {
        uint32_t sb = sbase + stage * STAGE_B;
        #pragma unroll
        for (int q = 0; q < 4; q++)
            load_slab(sb + q * SLAB_B, p * 64 + q * 16);
        CP_COMMIT();
    };

    int r = lane & 15, sel = lane >> 4;

    auto compute_slab = [&](uint32_t sb) {
        uint32_t sA = sb, sB = sb + TILE_B;
        uint32_t af[4][4];
        #pragma unroll
        for (int mi = 0; mi < 4; mi++) {
            int rowA = wm * 64 + mi * 16 + r;
            uint32_t off = rowA * PITCH_B + ((sel ^ ((rowA >> 2) & 1)) << 4);
            ldsm_x4(af[mi][0], af[mi][1], af[mi][2], af[mi][3], sA + off);
        }
        uint32_t bf[2][4];
        #pragma unroll
        for (int nj = 0; nj < 2; nj++) {
            int rowB = wn * 32 + nj * 16 + r;
            uint32_t off = rowB * PITCH_B + ((sel ^ ((rowB >> 2) & 1)) << 4);
            ldsm_x4(bf[nj][0], bf[nj][1], bf[nj][2], bf[nj][3], sB + off);
        }
        #pragma unroll
        for (int mi = 0; mi < 4; mi++) {
            #pragma unroll
            for (int nn = 0; nn < 4; nn++) {
                int nj = nn >> 1, hi8 = nn & 1;
                mma_fp16(acc[mi][nn], af[mi], bf[nj][hi8], bf[nj][hi8 + 2]);
            }
        }
    };

    load_quad(0, 0);

    for (int p = 0; p < nquad; p++) {
        if (p + 1 < nquad) load_quad((p + 1) & 1, p + 1);
        if (p + 1 < nquad) { CP_WAIT(1); } else { CP_WAIT(0); }
        __syncthreads();
        uint32_t sb = sbase + (p & 1) * STAGE_B;
        compute_slab(sb);
        compute_slab(sb + SLAB_B);
        compute_slab(sb + 2 * SLAB_B);
        compute_slab(sb + 3 * SLAB_B);
        __syncthreads();
    }

    // epilogue: bias + relu, store fp16
    int qr = lane >> 2, qc = lane & 3;
    #pragma unroll
    for (int nn = 0; nn < 4; nn++) {
        int col = n0 + wn * 32 + (nn >> 1) * 16 + (nn & 1) * 8 + qc * 2;
        float bz0 = __ldg(&bias[col]), bz1 = __ldg(&bias[col + 1]);
        #pragma unroll
        for (int mi = 0; mi < 4; mi++) {
            int row0 = m0 + wm * 64 + mi * 16 + qr;
            if (row0 < M) {
                __half2 hv = __floats2half2_rn(fmaxf(acc[mi][nn][0] + bz0, 0.f),
                                               fmaxf(acc[mi][nn][1] + bz1, 0.f));
                *(__half2*)(C + (size_t)row0 * 256 + col) = hv;
            }
            int row1 = row0 + 8;
            if (row1 < M) {
                __half2 hv = __floats2half2_rn(fmaxf(acc[mi][nn][2] + bz0, 0.f),
                                               fmaxf(acc[mi][nn][3] + bz1, 0.f));
                *(__half2*)(C + (size_t)row1 * 256 + col) = hv;
            }
        }
    }
}

// ---------------------------------------------------------------------------
// 6. fused segment-pool + head: block g sums H rows [gstart[g], gstart[g+1])
//    (sorted batch -> contiguous rows, no atomics), then fc1(relu) + fc2.
__global__ void poolhead_kernel(const __half* __restrict__ H,
                                const float* __restrict__ molwt, const float* __restrict__ nrings,
                                const float* __restrict__ fcW1, const float* __restrict__ fcb1,
                                const float* __restrict__ fcW2, const float* __restrict__ fcb2,
                                float* __restrict__ out) {
    int g = blockIdx.x;
    int t = threadIdx.x;  // 256: one column per thread
    int r0 = g_gstart[g], r1 = g_gstart[g + 1];

    float s = 0.0f;
    int r = r0;
    for (; r + 4 <= r1; r += 4) {
        float a0 = __half2float(H[(size_t)(r    ) * 256 + t]);
        float a1 = __half2float(H[(size_t)(r + 1) * 256 + t]);
        float a2 = __half2float(H[(size_t)(r + 2) * 256 + t]);
        float a3 = __half2float(H[(size_t)(r + 3) * 256 + t]);
        s += (a0 + a1) + (a2 + a3);
    }
    for (; r < r1; r++) s += __half2float(H[(size_t)r * 256 + t]);

    __shared__ float hg[258];
    __shared__ float h1[196];
    float c = fmaxf((float)(r1 - r0), 1.0f);
    hg[t] = s / c;
    if (t == 0) { hg[256] = molwt[g]; hg[257] = nrings[g]; }
    __syncthreads();
    if (t < 196) {
        float a = fcb1[t];
        #pragma unroll 4
        for (int k = 0; k < 258; k++) a += hg[k] * fcW1[k * 196 + t];
        h1[t] = fmaxf(a, 0.0f);
    }
    __syncthreads();
    if (t < 16) {
        float a = fcb2[t];
        #pragma unroll 4
        for (int k = 0; k < 196; k++) a += h1[k] * fcW2[k * 16 + t];
        out[g * 16 + t] = a;
    }
}

// ---------------------------------------------------------------------------
extern "C" void kernel_launch(void* const* d_in, const int* in_sizes, int n_in,
                              void* d_out, int out_size) {
    const float* x      = (const float*)d_in[0];
    const int*   ei     = (const int*)  d_in[1];
    const int*   batch  = (const int*)  d_in[2];
    const float* molwt  = (const float*)d_in[3];
    const float* nrings = (const float*)d_in[4];
    const float* W1 = (const float*)d_in[5];
    const float* b1 = (const float*)d_in[6];
    const float* W2 = (const float*)d_in[7];
    const float* b2 = (const float*)d_in[8];
    const float* W3 = (const float*)d_in[9];
    const float* b3 = (const float*)d_in[10];
    const float* fcW1 = (const float*)d_in[11];
    const float* fcb1 = (const float*)d_in[12];
    const float* fcW2 = (const float*)d_in[13];
    const float* fcb2 = (const float*)d_in[14];

    const int N = in_sizes[2];
    const int E = in_sizes[1] / 2;
    const int G = in_sizes[3];
    const int F_IN = in_sizes[0] / N;   // 128

    __half *A, *H, *X16, *W1t, *W2t, *W3t;
    cudaGetSymbolAddress((void**)&A, g_A);
    cudaGetSymbolAddress((void**)&H, g_H);
    cudaGetSymbolAddress((void**)&X16, g_x16);
    cudaGetSymbolAddress((void**)&W1t, g_W1t);
    cudaGetSymbolAddress((void**)&W2t, g_W2t);
    cudaGetSymbolAddress((void**)&W3t, g_W3t);

    const int GEMM_SMEM = 2 * STAGE_B;   // 65536
    cudaFuncSetAttribute(gemm_tc, cudaFuncAttributeMaxDynamicSharedMemorySize, GEMM_SMEM);

    int nb = (N + 1023) / 1024;
    dim3 ggrid(2, (N + 127) / 128);
    int aggblocks = (N + 7) / 8;   // 8 warps / block

    // setup (scratch resets handled by last readers each call)
    int stot = E + N + N * F_IN / 4 + F_IN * 256 + 2 * 256 * 256;
    setup_kernel<<<(stot + 255) / 256, 256>>>(ei, batch, x, X16, W1, W2, W3, E, N, F_IN, G);
    scan_p12<<<nb, 1024>>>(N, nb);
    scan_p3<<<nb, 1024>>>(N);
    int E2 = (E + 1) / 2;
    fill_kernel<<<(E2 + 255) / 256, 256>>>(ei, E);

    // layer 1: fp16 x -> A, GEMM -> H
    agg_f16<128><<<aggblocks, 256>>>(X16, A, N);
    gemm_tc<<<ggrid, 256, GEMM_SMEM>>>(A, W1t, b1, H, N, F_IN);
    // layer 2: H -> A, GEMM -> H  (A and H disjoint; safe)
    agg_f16<256><<<aggblocks, 256>>>(H, A, N);
    gemm_tc<<<ggrid, 256, GEMM_SMEM>>>(A, W2t, b2, H, N, HID);
    // layer 3: H -> A, GEMM -> H
    agg_f16<256><<<aggblocks, 256>>>(H, A, N);
    gemm_tc<<<ggrid, 256, GEMM_SMEM>>>(A, W3t, b3, H, N, HID);

    // fused sorted-segment pooling + head (no atomics)
    poolhead_kernel<<<G, 256>>>(H, molwt, nrings, fcW1, fcb1, fcW2, fcb2, (float*)d_out);
}